// round 15
// baseline (speedup 1.0000x reference)
#include <cuda_runtime.h>
#include <cuda_bf16.h>
#include <cstdint>
#include <math.h>

#define Bb 4
#define Tt 2048
#define Cc 1024
#define Hh 16
#define Dd 64
#define Mm (Bb*Tt)   /* 8192 rows */

// Scratch (device globals: allocation-free rule)
__device__ float g_q[Mm*Cc];
__device__ float g_k[Mm*Cc];
__device__ float g_cos[Tt*32];
__device__ float g_sin[Tt*32];
// bf16 hi/lo split operands
__device__ uint16_t g_xh[Mm*Cc];   // x split; later reused for attention output
__device__ uint16_t g_xl[Mm*Cc];
__device__ uint16_t g_wh[4*Cc*Cc];
__device__ uint16_t g_wl[4*Cc*Cc];
__device__ uint16_t g_qh[Mm*Cc];
__device__ uint16_t g_ql[Mm*Cc];
__device__ uint16_t g_kh[Mm*Cc];
__device__ uint16_t g_kl[Mm*Cc];
__device__ uint16_t g_vh[Mm*Cc];
__device__ uint16_t g_vl[Mm*Cc];

// ========================== helpers ===========================
__device__ __forceinline__ uint32_t smem_u32(const void* p)
{
    uint32_t a;
    asm("{ .reg .u64 t; cvta.to.shared.u64 t, %1; cvt.u32.u64 %0, t; }"
        : "=r"(a) : "l"(p));
    return a;
}

__device__ __forceinline__ void ldm4(uint32_t* r, uint32_t addr)
{
    asm volatile("ldmatrix.sync.aligned.m8n8.x4.shared.b16 {%0,%1,%2,%3}, [%4];"
                 : "=r"(r[0]), "=r"(r[1]), "=r"(r[2]), "=r"(r[3])
                 : "r"(addr));
}

__device__ __forceinline__ void ldm4t(uint32_t* r, uint32_t addr)
{
    asm volatile("ldmatrix.sync.aligned.m8n8.x4.trans.shared.b16 {%0,%1,%2,%3}, [%4];"
                 : "=r"(r[0]), "=r"(r[1]), "=r"(r[2]), "=r"(r[3])
                 : "r"(addr));
}

__device__ __forceinline__ void mma16816(float* d, const uint32_t* a,
                                         uint32_t b0, uint32_t b1)
{
    asm volatile(
        "mma.sync.aligned.m16n8k16.row.col.f32.bf16.bf16.f32 "
        "{%0,%1,%2,%3}, {%4,%5,%6,%7}, {%8,%9}, {%0,%1,%2,%3};"
        : "+f"(d[0]), "+f"(d[1]), "+f"(d[2]), "+f"(d[3])
        : "r"(a[0]), "r"(a[1]), "r"(a[2]), "r"(a[3]), "r"(b0), "r"(b1));
}

__device__ __forceinline__ void cp16(uint32_t dst, const void* src)
{
    asm volatile("cp.async.cg.shared.global [%0], [%1], 16;"
                 :: "r"(dst), "l"(src));
}
#define CP_COMMIT() asm volatile("cp.async.commit_group;" ::: "memory")
#define CP_WAIT2()  asm volatile("cp.async.wait_group 2;"  ::: "memory")
#define CP_WAIT1()  asm volatile("cp.async.wait_group 1;"  ::: "memory")
#define CP_WAIT0()  asm volatile("cp.async.wait_group 0;"  ::: "memory")

__device__ __forceinline__ void split4(float4 a, uint2& hi4, uint2& lo4)
{
    __nv_bfloat16 h0 = __float2bfloat16(a.x), h1 = __float2bfloat16(a.y);
    __nv_bfloat16 h2 = __float2bfloat16(a.z), h3 = __float2bfloat16(a.w);
    __nv_bfloat16 l0 = __float2bfloat16(a.x - __bfloat162float(h0));
    __nv_bfloat16 l1 = __float2bfloat16(a.y - __bfloat162float(h1));
    __nv_bfloat16 l2 = __float2bfloat16(a.z - __bfloat162float(h2));
    __nv_bfloat16 l3 = __float2bfloat16(a.w - __bfloat162float(h3));
    unsigned short u0 = *(unsigned short*)&h0, u1 = *(unsigned short*)&h1;
    unsigned short u2 = *(unsigned short*)&h2, u3 = *(unsigned short*)&h3;
    unsigned short v0 = *(unsigned short*)&l0, v1 = *(unsigned short*)&l1;
    unsigned short v2 = *(unsigned short*)&l2, v3 = *(unsigned short*)&l3;
    hi4.x = (uint32_t)u0 | ((uint32_t)u1 << 16);
    hi4.y = (uint32_t)u2 | ((uint32_t)u3 << 16);
    lo4.x = (uint32_t)v0 | ((uint32_t)v1 << 16);
    lo4.y = (uint32_t)v2 | ((uint32_t)v3 << 16);
}

__device__ __forceinline__ void split2pack(float x, float y,
                                           uint32_t& hp, uint32_t& lp)
{
    __nv_bfloat16 hx = __float2bfloat16(x), hy = __float2bfloat16(y);
    __nv_bfloat16 lx = __float2bfloat16(x - __bfloat162float(hx));
    __nv_bfloat16 ly = __float2bfloat16(y - __bfloat162float(hy));
    unsigned short a = *(unsigned short*)&hx, b = *(unsigned short*)&hy;
    unsigned short c = *(unsigned short*)&lx, d = *(unsigned short*)&ly;
    hp = (uint32_t)a | ((uint32_t)b << 16);
    lp = (uint32_t)c | ((uint32_t)d << 16);
}

// ---------------------------------------------------------------------------
// fp32 -> (hi, lo) bf16 split, elementwise.
// ---------------------------------------------------------------------------
__global__ void split_kernel(const float4* __restrict__ src,
                             uint2* __restrict__ hi, uint2* __restrict__ lo,
                             int n4)
{
    int i = blockIdx.x * blockDim.x + threadIdx.x;
    if (i < n4) {
        uint2 h4, l4;
        split4(src[i], h4, l4);
        hi[i] = h4;
        lo[i] = l4;
    }
}

// All four weights in one launch.
__global__ void split_w_kernel(const float4* __restrict__ w0,
                               const float4* __restrict__ w1,
                               const float4* __restrict__ w2,
                               const float4* __restrict__ w3,
                               uint2* __restrict__ hi, uint2* __restrict__ lo,
                               int n4each)
{
    int i = blockIdx.x * blockDim.x + threadIdx.x;
    if (i < 4 * n4each) {
        int w = i / n4each;
        int j = i - w * n4each;
        const float4* src = (w == 0) ? w0 : (w == 1) ? w1 : (w == 2) ? w2 : w3;
        uint2 h4, l4;
        split4(src[j], h4, l4);
        hi[i] = h4;
        lo[i] = l4;
    }
}

// ---------------------------------------------------------------------------
// Shared GEMM mainloop: BK=16 stages (SK=24, 48B rows), 4-stage ring,
// prefetch-before-compute, ONE sync per iter, 2 CTAs/SM.
// Accumulates d[2][8][4] for a 128x128 tile of sum_k A[m][k]*W[n][k].
// ---------------------------------------------------------------------------
#define SK 24
#define ARR_B (128*SK*2)         /* 6144 B per operand array */
#define STG_B (4*ARR_B)          /* 24576 B per stage */
#define NSTG 4
#define GBF_SMEM (NSTG*STG_B)    /* 98304 B -> 2 CTAs/SM */

#define ISSUE_STAGE(st, kb)                                                       \
    do {                                                                          \
        uint32_t sb_ = sbase + (uint32_t)(st) * STG_B;                            \
        int koff_ = (kb) * 16;                                                    \
        _Pragma("unroll")                                                         \
        for (int i_ = 0; i_ < 2; i_++) {                                          \
            int idx_ = tid + 256 * i_;                                            \
            if (idx_ < 384) {                                                     \
                int r_ = idx_ / 3;                                                \
                int c_ = idx_ - r_ * 3;                                           \
                uint32_t doff_ = (uint32_t)(r_ * 48 + c_ * 16);                   \
                size_t ga_ = (size_t)(row0 + r_) * Cc + koff_ + c_ * 8;           \
                size_t gw_ = (size_t)(col0 + r_) * Cc + koff_ + c_ * 8;           \
                cp16(sb_ + doff_,             Ah + ga_);                          \
                cp16(sb_ + ARR_B + doff_,     Al + ga_);                          \
                cp16(sb_ + 2*ARR_B + doff_,   Wh + gw_);                          \
                cp16(sb_ + 3*ARR_B + doff_,   Wl + gw_);                          \
            }                                                                     \
        }                                                                         \
    } while (0)

#define GEMM_MAINLOOP(Ah, Al, Wh, Wl, row0, col0)                                 \
    const uint32_t a_elem = (uint32_t)((warp_r*32 + (lane & 15)) * SK + (lane >> 4) * 8); \
    const uint32_t b_elem = (uint32_t)((warp_c*64 + (lane & 7) + ((lane >> 4) & 1) * 8) * SK \
                                       + ((lane >> 3) & 1) * 8);                  \
    ISSUE_STAGE(0, 0); CP_COMMIT();                                               \
    ISSUE_STAGE(1, 1); CP_COMMIT();                                               \
    ISSUE_STAGE(2, 2); CP_COMMIT();                                               \
    for (int kb = 0; kb < 64; kb++) {                                             \
        CP_WAIT2();                                                               \
        __syncthreads();                                                          \
        if (kb + 3 < 64) {                                                        \
            ISSUE_STAGE((kb + 3) & 3, kb + 3);                                    \
        }                                                                         \
        CP_COMMIT();                                                              \
        const uint32_t sb = sbase + (uint32_t)(kb & 3) * STG_B;                   \
        const uint32_t ah_b = sb;                                                 \
        const uint32_t al_b = sb + ARR_B;                                         \
        const uint32_t wh_b = sb + 2*ARR_B;                                       \
        const uint32_t wl_b = sb + 3*ARR_B;                                       \
        uint32_t ahf[2][4], alf[2][4];                                            \
        _Pragma("unroll")                                                         \
        for (int mt = 0; mt < 2; mt++) {                                          \
            uint32_t off = 2u * (a_elem + (uint32_t)mt * 16 * SK);                \
            ldm4(ahf[mt], ah_b + off);                                            \
            ldm4(alf[mt], al_b + off);                                            \
        }                                                                         \
        uint32_t bh[4][4], bl[4][4];                                              \
        _Pragma("unroll")                                                         \
        for (int g = 0; g < 4; g++) {                                             \
            uint32_t off = 2u * (b_elem + (uint32_t)g * 16 * SK);                 \
            ldm4(bh[g], wh_b + off);                                              \
            ldm4(bl[g], wl_b + off);                                              \
        }                                                                         \
        _Pragma("unroll")                                                         \
        for (int mt = 0; mt < 2; mt++) {                                          \
            _Pragma("unroll")                                                     \
            for (int g = 0; g < 4; g++) {                                         \
                mma16816(d[mt][2*g],   ahf[mt], bh[g][0], bh[g][1]);              \
                mma16816(d[mt][2*g+1], ahf[mt], bh[g][2], bh[g][3]);              \
                mma16816(d[mt][2*g],   ahf[mt], bl[g][0], bl[g][1]);              \
                mma16816(d[mt][2*g+1], ahf[mt], bl[g][2], bl[g][3]);              \
                mma16816(d[mt][2*g],   alf[mt], bh[g][0], bh[g][1]);              \
                mma16816(d[mt][2*g+1], alf[mt], bh[g][2], bh[g][3]);              \
            }                                                                     \
        }                                                                         \
    }

// ---------------------------------------------------------------------------
// Fused QKV GEMM: gridDim.z selects {Wq->q fp32, Wk->k fp32, Wv->mix->vh/vl}.
// ---------------------------------------------------------------------------
__global__ __launch_bounds__(256, 2) void gemm_qkv(
    const uint16_t* __restrict__ Ah, const uint16_t* __restrict__ Al,
    const uint16_t* __restrict__ WhB, const uint16_t* __restrict__ WlB,
    float* __restrict__ qout, float* __restrict__ kout,
    const float* __restrict__ v1, const float* __restrict__ lambp,
    uint16_t* __restrict__ vhout, uint16_t* __restrict__ vlout)
{
    extern __shared__ __align__(16) char dsm[];
    const uint32_t sbase = smem_u32(dsm);
    const int tid  = threadIdx.x;
    const int wid  = tid >> 5;
    const int lane = tid & 31;
    const int warp_r = wid & 3;
    const int warp_c = wid >> 2;
    const int row0 = blockIdx.x * 128;
    const int col0 = blockIdx.y * 128;
    const int z = blockIdx.z;
    const uint16_t* Wh = WhB + (size_t)z * Cc * Cc;
    const uint16_t* Wl = WlB + (size_t)z * Cc * Cc;

    float d[2][8][4];
    #pragma unroll
    for (int mt = 0; mt < 2; mt++)
        #pragma unroll
        for (int nt = 0; nt < 8; nt++)
            #pragma unroll
            for (int e = 0; e < 4; e++) d[mt][nt][e] = 0.f;

    GEMM_MAINLOOP(Ah, Al, Wh, Wl, row0, col0)

    const int rbase = row0 + warp_r * 32 + (lane >> 2);
    const int cbase = col0 + warp_c * 64 + (lane & 3) * 2;
    if (z < 2) {
        float* Cout = z ? kout : qout;
        #pragma unroll
        for (int mt = 0; mt < 2; mt++) {
            #pragma unroll
            for (int nt = 0; nt < 8; nt++) {
                int rr = rbase + mt * 16;
                int cc = cbase + nt * 8;
                *(float2*)(Cout + (size_t)rr * Cc + cc) =
                    make_float2(d[mt][nt][0], d[mt][nt][1]);
                *(float2*)(Cout + (size_t)(rr + 8) * Cc + cc) =
                    make_float2(d[mt][nt][2], d[mt][nt][3]);
            }
        }
    } else {
        const float lam = *lambp;
        #pragma unroll
        for (int mt = 0; mt < 2; mt++) {
            #pragma unroll
            for (int nt = 0; nt < 8; nt++) {
                int rr = rbase + mt * 16;
                int cc = cbase + nt * 8;
                size_t e0 = (size_t)rr * Cc + cc;
                size_t e1 = (size_t)(rr + 8) * Cc + cc;
                float2 m0 = *(const float2*)(v1 + e0);
                float2 m1 = *(const float2*)(v1 + e1);
                float a0 = (1.f - lam) * d[mt][nt][0] + lam * m0.x;
                float a1 = (1.f - lam) * d[mt][nt][1] + lam * m0.y;
                float a2 = (1.f - lam) * d[mt][nt][2] + lam * m1.x;
                float a3 = (1.f - lam) * d[mt][nt][3] + lam * m1.y;
                uint32_t hp, lp;
                split2pack(a0, a1, hp, lp);
                *(uint32_t*)(vhout + e0) = hp;
                *(uint32_t*)(vlout + e0) = lp;
                split2pack(a2, a3, hp, lp);
                *(uint32_t*)(vhout + e1) = hp;
                *(uint32_t*)(vlout + e1) = lp;
            }
        }
    }
}

// ---------------------------------------------------------------------------
// Proj GEMM (fp32 out, no mix) — same mainloop.
// ---------------------------------------------------------------------------
__global__ __launch_bounds__(256, 2) void gemm_bf(
    const uint16_t* __restrict__ Ah, const uint16_t* __restrict__ Al,
    const uint16_t* __restrict__ Wh, const uint16_t* __restrict__ Wl,
    float* __restrict__ Cout)
{
    extern __shared__ __align__(16) char dsm[];
    const uint32_t sbase = smem_u32(dsm);
    const int tid  = threadIdx.x;
    const int wid  = tid >> 5;
    const int lane = tid & 31;
    const int warp_r = wid & 3;
    const int warp_c = wid >> 2;
    const int row0 = blockIdx.x * 128;
    const int col0 = blockIdx.y * 128;

    float d[2][8][4];
    #pragma unroll
    for (int mt = 0; mt < 2; mt++)
        #pragma unroll
        for (int nt = 0; nt < 8; nt++)
            #pragma unroll
            for (int e = 0; e < 4; e++) d[mt][nt][e] = 0.f;

    GEMM_MAINLOOP(Ah, Al, Wh, Wl, row0, col0)

    const int rbase = row0 + warp_r * 32 + (lane >> 2);
    const int cbase = col0 + warp_c * 64 + (lane & 3) * 2;
    #pragma unroll
    for (int mt = 0; mt < 2; mt++) {
        #pragma unroll
        for (int nt = 0; nt < 8; nt++) {
            int rr = rbase + mt * 16;
            int cc = cbase + nt * 8;
            *(float2*)(Cout + (size_t)rr * Cc + cc) =
                make_float2(d[mt][nt][0], d[mt][nt][1]);
            *(float2*)(Cout + (size_t)(rr + 8) * Cc + cc) =
                make_float2(d[mt][nt][2], d[mt][nt][3]);
        }
    }
}

// ---------------------------------------------------------------------------
// RoPE tables (fp64 trig; immune to --use_fast_math substitution).
// ---------------------------------------------------------------------------
__global__ void rope_table_kernel(float* __restrict__ ctab,
                                  float* __restrict__ stab)
{
    int t    = blockIdx.x;
    int lane = threadIdx.x;
    float invf = (float)exp2(-(double)lane * (13.287712379549449 / 32.0));
    float fr   = __fmul_rn((float)t, invf);
    ctab[t * 32 + lane] = (float)cos((double)fr);
    stab[t * 32 + lane] = (float)sin((double)fr);
}

// ---------------------------------------------------------------------------
// RMSNorm + RoPE, fp32 in -> hi/lo bf16 out (q pre-scaled by 0.125).
// ---------------------------------------------------------------------------
__global__ __launch_bounds__(256) void rmsrope_split(
    const float* __restrict__ qsrc, const float* __restrict__ ksrc,
    uint16_t* __restrict__ qh, uint16_t* __restrict__ ql,
    uint16_t* __restrict__ kh, uint16_t* __restrict__ kl,
    const float* __restrict__ ctab, const float* __restrict__ stab)
{
    const int isk = blockIdx.y;
    const float* src = isk ? ksrc : qsrc;
    uint16_t* dh = isk ? kh : qh;
    uint16_t* dl = isk ? kl : ql;
    const float scale = isk ? 1.0f : 0.125f;

    const int warp = threadIdx.x >> 5;
    const int lane = threadIdx.x & 31;
    const int row  = blockIdx.x * 8 + warp;
    const int t    = (row / Hh) % Tt;

    const float* base = src + (size_t)row * 64;
    float x1 = base[lane];
    float x2 = base[lane + 32];

    float ss = x1 * x1 + x2 * x2;
    #pragma unroll
    for (int off = 16; off; off >>= 1)
        ss += __shfl_xor_sync(0xffffffffu, ss, off);

    float r = rsqrtf(ss * (1.0f / 64.0f) + 1.1920929e-7f);
    float c = __ldg(&ctab[t * 32 + lane]);
    float s = __ldg(&stab[t * 32 + lane]);

    float n1 = x1 * r, n2 = x2 * r;
    float y1 = (n1 * c + n2 * s) * scale;
    float y2 = (n2 * c - n1 * s) * scale;

    size_t o = (size_t)row * 64;
    __nv_bfloat16 h1 = __float2bfloat16(y1);
    __nv_bfloat16 h2 = __float2bfloat16(y2);
    __nv_bfloat16 l1 = __float2bfloat16(y1 - __bfloat162float(h1));
    __nv_bfloat16 l2 = __float2bfloat16(y2 - __bfloat162float(h2));
    dh[o + lane]      = *(unsigned short*)&h1;
    dh[o + lane + 32] = *(unsigned short*)&h2;
    dl[o + lane]      = *(unsigned short*)&l1;
    dl[o + lane + 32] = *(unsigned short*)&l2;
}

// ---------------------------------------------------------------------------
// Flash attention on mma.sync (bf16 hi/lo split), causal, online softmax.
// CTA: 128 queries x one (b,h). Key tiles of 32, double-buffered; 2 CTAs/SM.
// ---------------------------------------------------------------------------
#define FROWB 144              /* 72-element padded row, bytes */
#define F_QL 18432             /* Q lo array offset (Q hi at 0) */
#define F_STG 36864            /* Q region total; KV stages follow */
#define F_KV 4608              /* one KV array: 32 rows x 144 B */
#define F_STGB (4*F_KV)        /* stage: Kh,Kl,Vh,Vl = 18432 B */
#define FLASH_SMEM (F_STG + 2*F_STGB)   /* 73728 -> 2 CTAs/SM */

__global__ __launch_bounds__(256, 2) void flash_mma(
    const uint16_t* __restrict__ qh, const uint16_t* __restrict__ ql,
    const uint16_t* __restrict__ kh, const uint16_t* __restrict__ kl,
    const uint16_t* __restrict__ vh, const uint16_t* __restrict__ vl,
    uint16_t* __restrict__ oh, uint16_t* __restrict__ ol)
{
    extern __shared__ __align__(16) char fsm[];
    const uint32_t sb = smem_u32(fsm);
    const int tid = threadIdx.x;
    const int wid = tid >> 5;
    const int lane = tid & 31;
    const int qblk = gridDim.x - 1 - blockIdx.x;     // heavy first
    const int bh = blockIdx.y;
    const int b = bh >> 4, h = bh & 15;
    const int q0 = qblk * 128;
    const int nkt = 4 * qblk + 4;
    const size_t rowbase = (size_t)b * Tt * Cc + (size_t)h * Dd;

    // stage loader: K/V hi+lo, 32 rows x 128B each (1 chunk per thread/array)
    #define F_ISSUE(st, kt)                                                     \
    do {                                                                        \
        uint32_t s_ = sb + F_STG + (uint32_t)(st) * F_STGB;                     \
        int k0_ = (kt) * 32;                                                    \
        int r_ = tid >> 3, cq_ = tid & 7;                                       \
        size_t g_ = rowbase + (size_t)(k0_ + r_) * Cc + cq_ * 8;                \
        uint32_t d_ = s_ + (uint32_t)(r_ * FROWB + cq_ * 16);                   \
        cp16(d_,           kh + g_);                                            \
        cp16(d_ +   F_KV,  kl + g_);                                            \
        cp16(d_ + 2*F_KV,  vh + g_);                                            \
        cp16(d_ + 3*F_KV,  vl + g_);                                            \
    } while (0)

    // Prologue: Q (128 rows x 128B, hi+lo) + stage 0 in one group
    #pragma unroll
    for (int i = 0; i < 4; i++) {
        int c = tid + 256 * i;
        int r = c >> 3, cq = c & 7;
        size_t g = rowbase + (size_t)(q0 + r) * Cc + cq * 8;
        uint32_t d = sb + (uint32_t)(r * FROWB + cq * 16);
        cp16(d, qh + g);
        cp16(d + F_QL, ql + g);
    }
    F_ISSUE(0, 0);
    CP_COMMIT();

    const uint32_t a_off = (uint32_t)((16*wid + (lane & 15)) * FROWB + (lane >> 4) * 16);
    const uint32_t bk_off = (uint32_t)(((lane & 7) + ((lane >> 4) & 1) * 8) * FROWB
                                       + ((lane >> 3) & 1) * 16);
    const uint32_t bv_off = (uint32_t)(((lane & 7) + ((lane >> 3) & 1) * 8) * FROWB
                                       + ((lane >> 4) & 1) * 16);

    uint32_t qfh[4][4], qfl[4][4];
    float o[8][4];
    #pragma unroll
    for (int j = 0; j < 8; j++)
        #pragma unroll
        for (int e = 0; e < 4; e++) o[j][e] = 0.f;
    float mrow[2] = {-1e30f, -1e30f};
    float lrow[2] = {0.f, 0.f};

    for (int kt = 0; kt < nkt; kt++) {
        if (kt + 1 < nkt) {
            F_ISSUE((kt + 1) & 1, kt + 1);
            CP_COMMIT();
            CP_WAIT1();
        } else {
            CP_WAIT0();
        }
        __syncthreads();

        if (kt == 0) {
            #pragma unroll
            for (int ks = 0; ks < 4; ks++) {
                ldm4(qfh[ks], sb + a_off + ks * 32);
                ldm4(qfl[ks], sb + F_QL + a_off + ks * 32);
            }
        }

        const uint32_t stg = sb + F_STG + (uint32_t)(kt & 1) * F_STGB;

        // S (128q x 32k) = Qh*Kh + Qh*Kl + Ql*Kh
        float s[4][4];
        #pragma unroll
        for (int j = 0; j < 4; j++)
            #pragma unroll
            for (int e = 0; e < 4; e++) s[j][e] = 0.f;

        #pragma unroll
        for (int ks = 0; ks < 4; ks++) {
            #pragma unroll
            for (int g = 0; g < 2; g++) {
                uint32_t khf[4], klf[4];
                uint32_t off = bk_off + (uint32_t)g * 16 * FROWB + (uint32_t)ks * 32;
                ldm4(khf, stg + off);
                ldm4(klf, stg + F_KV + off);
                mma16816(s[2*g],   qfh[ks], khf[0], khf[1]);
                mma16816(s[2*g+1], qfh[ks], khf[2], khf[3]);
                mma16816(s[2*g],   qfh[ks], klf[0], klf[1]);
                mma16816(s[2*g+1], qfh[ks], klf[2], klf[3]);
                mma16816(s[2*g],   qfl[ks], khf[0], khf[1]);
                mma16816(s[2*g+1], qfl[ks], khf[2], khf[3]);
            }
        }

        // causal mask (only the last 4 key tiles can cross the diagonal)
        if (kt >= 4 * qblk) {
            int qg0 = q0 + 16 * wid + (lane >> 2);
            int kgb = kt * 32 + (lane & 3) * 2;
            #pragma unroll
            for (int j = 0; j < 4; j++) {
                int kg = kgb + j * 8;
                if (kg     > qg0)     s[j][0] = -1e30f;
                if (kg + 1 > qg0)     s[j][1] = -1e30f;
                if (kg     > qg0 + 8) s[j][2] = -1e30f;
                if (kg + 1 > qg0 + 8) s[j][3] = -1e30f;
            }
        }

        // online softmax (rows r = lane>>2 and r+8)
        float tm0 = -1e30f, tm1 = -1e30f;
        #pragma unroll
        for (int j = 0; j < 4; j++) {
            tm0 = fmaxf(tm0, fmaxf(s[j][0], s[j][1]));
            tm1 = fmaxf(tm1, fmaxf(s[j][2], s[j][3]));
        }
        tm0 = fmaxf(tm0, __shfl_xor_sync(0xffffffffu, tm0, 1));
        tm0 = fmaxf(tm0, __shfl_xor_sync(0xffffffffu, tm0, 2));
        tm1 = fmaxf(tm1, __shfl_xor_sync(0xffffffffu, tm1, 1));
        tm1 = fmaxf(tm1, __shfl_xor_sync(0xffffffffu, tm1, 2));
        float mn0 = fmaxf(mrow[0], tm0);
        float mn1 = fmaxf(mrow[1], tm1);
        float al0 = __expf(mrow[0] - mn0);
        float al1 = __expf(mrow[1] - mn1);
        float rs0 = 0.f, rs1 = 0.f;
        #pragma unroll
        for (int j = 0; j < 4; j++) {
            s[j][0] = __expf(s[j][0] - mn0);
            s[j][1] = __expf(s[j][1] - mn0);
            s[j][2] = __expf(s[j][2] - mn1);
            s[j][3] = __expf(s[j][3] - mn1);
            rs0 += s[j][0] + s[j][1];
            rs1 += s[j][2] + s[j][3];
        }
        rs0 += __shfl_xor_sync(0xffffffffu, rs0, 1);
        rs0 += __shfl_xor_sync(0xffffffffu, rs0, 2);
        rs1 += __shfl_xor_sync(0xffffffffu, rs1, 1);
        rs1 += __shfl_xor_sync(0xffffffffu, rs1, 2);
        lrow[0] = lrow[0] * al0 + rs0;
        lrow[1] = lrow[1] * al1 + rs1;
        mrow[0] = mn0;
        mrow[1] = mn1;
        #pragma unroll
        for (int j = 0; j < 8; j++) {
            o[j][0] *= al0; o[j][1] *= al0;
            o[j][2] *= al1; o[j][3] *= al1;
        }

        // P fragments (hi/lo), reusing the S accumulator layout as A layout
        uint32_t pfh[2][4], pfl[2][4];
        #pragma unroll
        for (int ks = 0; ks < 2; ks++) {
            split2pack(s[2*ks][0],   s[2*ks][1],   pfh[ks][0], pfl[ks][0]);
            split2pack(s[2*ks][2],   s[2*ks][3],   pfh[ks][1], pfl[ks][1]);
            split2pack(s[2*ks+1][0], s[2*ks+1][1], pfh[ks][2], pfl[ks][2]);
            split2pack(s[2*ks+1][2], s[2*ks+1][3], pfh[ks][3], pfl[ks][3]);
        }

        // O += Ph*Vh + Ph*Vl + Pl*Vh  (V via ldmatrix.trans from [key][dim])
        #pragma unroll
        for (int ks = 0; ks < 2; ks++) {
            #pragma unroll
            for (int g = 0; g < 4; g++) {
                uint32_t vhf[4], vlf[4];
                uint32_t off = bv_off + (uint32_t)ks * 16 * FROWB + (uint32_t)g * 32;
                ldm4t(vhf, stg + 2*F_KV + off);
                ldm4t(vlf, stg + 3*F_KV + off);
                mma16816(o[2*g],   pfh[ks], vhf[0], vhf[1]);
                mma16816(o[2*g+1], pfh[ks], vhf[2], vhf[3]);
                mma16816(o[2*g],   pfh[ks], vlf[0], vlf[1]);
                mma16816(o[2*g+1], pfh[ks], vlf[2], vlf[3]);
                mma16816(o[2*g],   pfl[ks], vhf[0], vhf[1]);
                mma16816(o[2*g+1], pfl[ks], vhf[2], vhf[3]);
            }
        }
        __syncthreads();
    }
    #undef F_ISSUE

    float inv0 = 1.0f / lrow[0];
    float inv1 = 1.0f / lrow[1];
    int t0 = q0 + 16 * wid + (lane >> 2);
    int t1 = t0 + 8;
    #pragma unroll
    for (int j = 0; j < 8; j++) {
        int cb = j * 8 + (lane & 3) * 2;
        size_t e0 = rowbase + (size_t)t0 * Cc + cb;
        size_t e1 = rowbase + (size_t)t1 * Cc + cb;
        uint32_t hp, lp;
        split2pack(o[j][0] * inv0, o[j][1] * inv0, hp, lp);
        *(uint32_t*)(oh + e0) = hp;
        *(uint32_t*)(ol + e0) = lp;
        split2pack(o[j][2] * inv1, o[j][3] * inv1, hp, lp);
        *(uint32_t*)(oh + e1) = hp;
        *(uint32_t*)(ol + e1) = lp;
    }
}

// ---------------------------------------------------------------------------
__global__ void copy_kernel(const float4* __restrict__ src,
                            float4* __restrict__ dst, int n4)
{
    for (int i = blockIdx.x * blockDim.x + threadIdx.x; i < n4;
         i += gridDim.x * blockDim.x)
        dst[i] = src[i];
}

// ---------------------------------------------------------------------------
extern "C" void kernel_launch(void* const* d_in, const int* in_sizes, int n_in,
                              void* d_out, int out_size)
{
    const float *x, *v1, *Wq, *Wk, *Wv, *Wp, *lamb;
    if (in_sizes[0] == Mm * Cc) {            // dict order
        x    = (const float*)d_in[0];
        v1   = (const float*)d_in[1];
        Wq   = (const float*)d_in[2];
        Wk   = (const float*)d_in[3];
        Wv   = (const float*)d_in[4];
        Wp   = (const float*)d_in[5];
        lamb = (const float*)d_in[6];
    } else {                                  // alphabetical order
        Wk   = (const float*)d_in[0];
        Wp   = (const float*)d_in[1];
        Wq   = (const float*)d_in[2];
        Wv   = (const float*)d_in[3];
        lamb = (const float*)d_in[4];
        v1   = (const float*)d_in[5];
        x    = (const float*)d_in[6];
    }
    float* out = (float*)d_out;

    float *q, *k, *ctab, *stab;
    uint16_t *xh, *xl, *wh, *wl, *qhp, *qlp, *khp, *klp, *vhp, *vlp;
    cudaGetSymbolAddress((void**)&q,    g_q);
    cudaGetSymbolAddress((void**)&k,    g_k);
    cudaGetSymbolAddress((void**)&ctab, g_cos);
    cudaGetSymbolAddress((void**)&stab, g_sin);
    cudaGetSymbolAddress((void**)&xh,   g_xh);
    cudaGetSymbolAddress((void**)&xl,   g_xl);
    cudaGetSymbolAddress((void**)&wh,   g_wh);
    cudaGetSymbolAddress((void**)&wl,   g_wl);
    cudaGetSymbolAddress((void**)&qhp,  g_qh);
    cudaGetSymbolAddress((void**)&qlp,  g_ql);
    cudaGetSymbolAddress((void**)&khp,  g_kh);
    cudaGetSymbolAddress((void**)&klp,  g_kl);
    cudaGetSymbolAddress((void**)&vhp,  g_vh);
    cudaGetSymbolAddress((void**)&vlp,  g_vl);

    rope_table_kernel<<<Tt, 32>>>(ctab, stab);

    const int nx4 = Mm * Cc / 4;
    const int nw4 = Cc * Cc / 4;
    split_kernel<<<(nx4 + 255) / 256, 256>>>((const float4*)x,
        (uint2*)xh, (uint2*)xl, nx4);
    split_w_kernel<<<(4 * nw4 + 255) / 256, 256>>>(
        (const float4*)Wq, (const float4*)Wk, (const float4*)Wv,
        (const float4*)Wp, (uint2*)wh, (uint2*)wl, nw4);

    cudaFuncSetAttribute(gemm_qkv,
                         cudaFuncAttributeMaxDynamicSharedMemorySize, GBF_SMEM);
    cudaFuncSetAttribute(gemm_bf,
                         cudaFuncAttributeMaxDynamicSharedMemorySize, GBF_SMEM);

    gemm_qkv<<<dim3(Mm / 128, Cc / 128, 3), 256, GBF_SMEM>>>(
        xh, xl, wh, wl, q, k, v1, lamb, vhp, vlp);

    rmsrope_split<<<dim3(Bb * Tt * Hh / 8, 2), 256>>>(q, k, qhp, qlp, khp, klp,
                                                      ctab, stab);

    cudaFuncSetAttribute(flash_mma,
                         cudaFuncAttributeMaxDynamicSharedMemorySize, FLASH_SMEM);
    flash_mma<<<dim3(Tt / 128, Bb * Hh), 256, FLASH_SMEM>>>(
        qhp, qlp, khp, klp, vhp, vlp, xh, xl);

    gemm_bf<<<dim3(Mm / 128, Cc / 128), 256, GBF_SMEM>>>(
        xh, xl, wh + 3ll*Cc*Cc, wl + 3ll*Cc*Cc, out);

    if (out_size >= 2 * Mm * Cc)
        copy_kernel<<<2048, 256>>>((const float4*)v1,
                                   (float4*)(out + (size_t)Mm * Cc),
                                   (Mm * Cc) / 4);
}

// round 16
// speedup vs baseline: 1.0573x; 1.0573x over previous
#include <cuda_runtime.h>
#include <cuda_bf16.h>
#include <cstdint>
#include <math.h>

#define Bb 4
#define Tt 2048
#define Cc 1024
#define Hh 16
#define Dd 64
#define Mm (Bb*Tt)   /* 8192 rows */

// Scratch (device globals: allocation-free rule)
__device__ float g_q[Mm*Cc];
__device__ float g_k[Mm*Cc];
__device__ float g_cos[Tt*32];
__device__ float g_sin[Tt*32];
// bf16 hi/lo split operands
__device__ uint16_t g_xh[Mm*Cc];   // x split; later reused for attention output
__device__ uint16_t g_xl[Mm*Cc];
__device__ uint16_t g_wh[4*Cc*Cc];
__device__ uint16_t g_wl[4*Cc*Cc];
__device__ uint16_t g_qh[Mm*Cc];
__device__ uint16_t g_ql[Mm*Cc];
__device__ uint16_t g_kh[Mm*Cc];
__device__ uint16_t g_kl[Mm*Cc];
__device__ uint16_t g_vh[Mm*Cc];
__device__ uint16_t g_vl[Mm*Cc];

// ========================== helpers ===========================
__device__ __forceinline__ uint32_t smem_u32(const void* p)
{
    uint32_t a;
    asm("{ .reg .u64 t; cvta.to.shared.u64 t, %1; cvt.u32.u64 %0, t; }"
        : "=r"(a) : "l"(p));
    return a;
}

__device__ __forceinline__ void ldm4(uint32_t* r, uint32_t addr)
{
    asm volatile("ldmatrix.sync.aligned.m8n8.x4.shared.b16 {%0,%1,%2,%3}, [%4];"
                 : "=r"(r[0]), "=r"(r[1]), "=r"(r[2]), "=r"(r[3])
                 : "r"(addr));
}

__device__ __forceinline__ void ldm4t(uint32_t* r, uint32_t addr)
{
    asm volatile("ldmatrix.sync.aligned.m8n8.x4.trans.shared.b16 {%0,%1,%2,%3}, [%4];"
                 : "=r"(r[0]), "=r"(r[1]), "=r"(r[2]), "=r"(r[3])
                 : "r"(addr));
}

__device__ __forceinline__ void mma16816(float* d, const uint32_t* a,
                                         uint32_t b0, uint32_t b1)
{
    asm volatile(
        "mma.sync.aligned.m16n8k16.row.col.f32.bf16.bf16.f32 "
        "{%0,%1,%2,%3}, {%4,%5,%6,%7}, {%8,%9}, {%0,%1,%2,%3};"
        : "+f"(d[0]), "+f"(d[1]), "+f"(d[2]), "+f"(d[3])
        : "r"(a[0]), "r"(a[1]), "r"(a[2]), "r"(a[3]), "r"(b0), "r"(b1));
}

__device__ __forceinline__ void cp16(uint32_t dst, const void* src)
{
    asm volatile("cp.async.cg.shared.global [%0], [%1], 16;"
                 :: "r"(dst), "l"(src));
}
#define CP_COMMIT() asm volatile("cp.async.commit_group;" ::: "memory")
#define CP_WAIT1()  asm volatile("cp.async.wait_group 1;"  ::: "memory")
#define CP_WAIT0()  asm volatile("cp.async.wait_group 0;"  ::: "memory")

__device__ __forceinline__ void split4(float4 a, uint2& hi4, uint2& lo4)
{
    __nv_bfloat16 h0 = __float2bfloat16(a.x), h1 = __float2bfloat16(a.y);
    __nv_bfloat16 h2 = __float2bfloat16(a.z), h3 = __float2bfloat16(a.w);
    __nv_bfloat16 l0 = __float2bfloat16(a.x - __bfloat162float(h0));
    __nv_bfloat16 l1 = __float2bfloat16(a.y - __bfloat162float(h1));
    __nv_bfloat16 l2 = __float2bfloat16(a.z - __bfloat162float(h2));
    __nv_bfloat16 l3 = __float2bfloat16(a.w - __bfloat162float(h3));
    unsigned short u0 = *(unsigned short*)&h0, u1 = *(unsigned short*)&h1;
    unsigned short u2 = *(unsigned short*)&h2, u3 = *(unsigned short*)&h3;
    unsigned short v0 = *(unsigned short*)&l0, v1 = *(unsigned short*)&l1;
    unsigned short v2 = *(unsigned short*)&l2, v3 = *(unsigned short*)&l3;
    hi4.x = (uint32_t)u0 | ((uint32_t)u1 << 16);
    hi4.y = (uint32_t)u2 | ((uint32_t)u3 << 16);
    lo4.x = (uint32_t)v0 | ((uint32_t)v1 << 16);
    lo4.y = (uint32_t)v2 | ((uint32_t)v3 << 16);
}

__device__ __forceinline__ void split2pack(float x, float y,
                                           uint32_t& hp, uint32_t& lp)
{
    __nv_bfloat16 hx = __float2bfloat16(x), hy = __float2bfloat16(y);
    __nv_bfloat16 lx = __float2bfloat16(x - __bfloat162float(hx));
    __nv_bfloat16 ly = __float2bfloat16(y - __bfloat162float(hy));
    unsigned short a = *(unsigned short*)&hx, b = *(unsigned short*)&hy;
    unsigned short c = *(unsigned short*)&lx, d = *(unsigned short*)&ly;
    hp = (uint32_t)a | ((uint32_t)b << 16);
    lp = (uint32_t)c | ((uint32_t)d << 16);
}

// ---------------------------------------------------------------------------
// fp32 -> (hi, lo) bf16 split, elementwise.
// ---------------------------------------------------------------------------
__global__ void split_kernel(const float4* __restrict__ src,
                             uint2* __restrict__ hi, uint2* __restrict__ lo,
                             int n4)
{
    int i = blockIdx.x * blockDim.x + threadIdx.x;
    if (i < n4) {
        uint2 h4, l4;
        split4(src[i], h4, l4);
        hi[i] = h4;
        lo[i] = l4;
    }
}

// All four weights in one launch.
__global__ void split_w_kernel(const float4* __restrict__ w0,
                               const float4* __restrict__ w1,
                               const float4* __restrict__ w2,
                               const float4* __restrict__ w3,
                               uint2* __restrict__ hi, uint2* __restrict__ lo,
                               int n4each)
{
    int i = blockIdx.x * blockDim.x + threadIdx.x;
    if (i < 4 * n4each) {
        int w = i / n4each;
        int j = i - w * n4each;
        const float4* src = (w == 0) ? w0 : (w == 1) ? w1 : (w == 2) ? w2 : w3;
        uint2 h4, l4;
        split4(src[j], h4, l4);
        hi[i] = h4;
        lo[i] = l4;
    }
}

// ---------------------------------------------------------------------------
// Shared GEMM mainloop, 2-stage ring, BK=32 (R14 proven config; 2 CTAs/SM).
// Accumulates d[2][8][4] for a 128x128 tile of sum_k A[m][k]*W[n][k].
// ---------------------------------------------------------------------------
#define SK 40
#define ARR_B (128*SK*2)
#define STG_B (4*ARR_B)
#define NSTG 2
#define GBF_SMEM (NSTG*STG_B)    /* 81920 B -> 2 CTAs/SM */

#define ISSUE_STAGE(st, kb)                                                       \
    do {                                                                          \
        uint32_t sb_ = sbase + (uint32_t)(st) * STG_B;                            \
        int koff_ = (kb) * 32;                                                    \
        { int r_ = cr0;                                                           \
          uint32_t doff_ = (uint32_t)(r_ * 80 + cc0 * 16);                        \
          size_t ga_ = (size_t)(row0 + r_) * Cc + koff_ + cc0 * 8;                \
          size_t gw_ = (size_t)(col0 + r_) * Cc + koff_ + cc0 * 8;                \
          cp16(sb_ + doff_,             Ah + ga_);                                \
          cp16(sb_ + ARR_B + doff_,     Al + ga_);                                \
          cp16(sb_ + 2*ARR_B + doff_,   Wh + gw_);                                \
          cp16(sb_ + 3*ARR_B + doff_,   Wl + gw_); }                              \
        { int r_ = cr0 + 64;                                                      \
          uint32_t doff_ = (uint32_t)(r_ * 80 + cc0 * 16);                        \
          size_t ga_ = (size_t)(row0 + r_) * Cc + koff_ + cc0 * 8;                \
          size_t gw_ = (size_t)(col0 + r_) * Cc + koff_ + cc0 * 8;                \
          cp16(sb_ + doff_,             Ah + ga_);                                \
          cp16(sb_ + ARR_B + doff_,     Al + ga_);                                \
          cp16(sb_ + 2*ARR_B + doff_,   Wh + gw_);                                \
          cp16(sb_ + 3*ARR_B + doff_,   Wl + gw_); }                              \
    } while (0)

#define GEMM_MAINLOOP(Ah, Al, Wh, Wl, row0, col0)                                 \
    const uint32_t a_elem = (uint32_t)((warp_r*32 + (lane & 15)) * SK + (lane >> 4) * 8); \
    const uint32_t b_elem = (uint32_t)((warp_c*64 + (lane & 7) + ((lane >> 4) & 1) * 8) * SK \
                                       + ((lane >> 3) & 1) * 8);                  \
    const int cr0 = tid >> 2;                                                     \
    const int cc0 = tid & 3;                                                      \
    ISSUE_STAGE(0, 0); CP_COMMIT();                                               \
    ISSUE_STAGE(1, 1); CP_COMMIT();                                               \
    for (int kb = 0; kb < 32; kb++) {                                             \
        CP_WAIT1();                                                               \
        __syncthreads();                                                          \
        const uint32_t sb = sbase + (uint32_t)(kb & 1) * STG_B;                   \
        const uint32_t ah_b = sb;                                                 \
        const uint32_t al_b = sb + ARR_B;                                         \
        const uint32_t wh_b = sb + 2*ARR_B;                                       \
        const uint32_t wl_b = sb + 3*ARR_B;                                       \
        _Pragma("unroll")                                                         \
        for (int ks = 0; ks < 2; ks++) {                                          \
            uint32_t ahf[2][4], alf[2][4];                                        \
            _Pragma("unroll")                                                     \
            for (int mt = 0; mt < 2; mt++) {                                      \
                uint32_t off = 2u * (a_elem + (uint32_t)mt * 16 * SK + (uint32_t)ks * 16); \
                ldm4(ahf[mt], ah_b + off);                                        \
                ldm4(alf[mt], al_b + off);                                        \
            }                                                                     \
            uint32_t bh[4][4], bl[4][4];                                          \
            _Pragma("unroll")                                                     \
            for (int g = 0; g < 4; g++) {                                         \
                uint32_t off = 2u * (b_elem + (uint32_t)g * 16 * SK + (uint32_t)ks * 16); \
                ldm4(bh[g], wh_b + off);                                          \
                ldm4(bl[g], wl_b + off);                                          \
            }                                                                     \
            _Pragma("unroll")                                                     \
            for (int mt = 0; mt < 2; mt++) {                                      \
                _Pragma("unroll")                                                 \
                for (int g = 0; g < 4; g++) {                                     \
                    mma16816(d[mt][2*g],   ahf[mt], bh[g][0], bh[g][1]);          \
                    mma16816(d[mt][2*g+1], ahf[mt], bh[g][2], bh[g][3]);          \
                    mma16816(d[mt][2*g],   ahf[mt], bl[g][0], bl[g][1]);          \
                    mma16816(d[mt][2*g+1], ahf[mt], bl[g][2], bl[g][3]);          \
                    mma16816(d[mt][2*g],   alf[mt], bh[g][0], bh[g][1]);          \
                    mma16816(d[mt][2*g+1], alf[mt], bh[g][2], bh[g][3]);          \
                }                                                                 \
            }                                                                     \
        }                                                                         \
        __syncthreads();                                                          \
        if (kb + 2 < 32) {                                                        \
            ISSUE_STAGE(kb & 1, kb + 2);                                          \
            CP_COMMIT();                                                          \
        }                                                                         \
    }

// ---------------------------------------------------------------------------
// Fused QKV GEMM: gridDim.z selects {Wq->q fp32, Wk->k fp32, Wv->mix->vh/vl}.
// ---------------------------------------------------------------------------
__global__ __launch_bounds__(256, 2) void gemm_qkv(
    const uint16_t* __restrict__ Ah, const uint16_t* __restrict__ Al,
    const uint16_t* __restrict__ WhB, const uint16_t* __restrict__ WlB,
    float* __restrict__ qout, float* __restrict__ kout,
    const float* __restrict__ v1, const float* __restrict__ lambp,
    uint16_t* __restrict__ vhout, uint16_t* __restrict__ vlout)
{
    extern __shared__ __align__(16) char dsm[];
    const uint32_t sbase = smem_u32(dsm);
    const int tid  = threadIdx.x;
    const int wid  = tid >> 5;
    const int lane = tid & 31;
    const int warp_r = wid & 3;
    const int warp_c = wid >> 2;
    const int row0 = blockIdx.x * 128;
    const int col0 = blockIdx.y * 128;
    const int z = blockIdx.z;
    const uint16_t* Wh = WhB + (size_t)z * Cc * Cc;
    const uint16_t* Wl = WlB + (size_t)z * Cc * Cc;

    float d[2][8][4];
    #pragma unroll
    for (int mt = 0; mt < 2; mt++)
        #pragma unroll
        for (int nt = 0; nt < 8; nt++)
            #pragma unroll
            for (int e = 0; e < 4; e++) d[mt][nt][e] = 0.f;

    GEMM_MAINLOOP(Ah, Al, Wh, Wl, row0, col0)

    const int rbase = row0 + warp_r * 32 + (lane >> 2);
    const int cbase = col0 + warp_c * 64 + (lane & 3) * 2;
    if (z < 2) {
        float* Cout = z ? kout : qout;
        #pragma unroll
        for (int mt = 0; mt < 2; mt++) {
            #pragma unroll
            for (int nt = 0; nt < 8; nt++) {
                int rr = rbase + mt * 16;
                int cc = cbase + nt * 8;
                *(float2*)(Cout + (size_t)rr * Cc + cc) =
                    make_float2(d[mt][nt][0], d[mt][nt][1]);
                *(float2*)(Cout + (size_t)(rr + 8) * Cc + cc) =
                    make_float2(d[mt][nt][2], d[mt][nt][3]);
            }
        }
    } else {
        const float lam = *lambp;
        #pragma unroll
        for (int mt = 0; mt < 2; mt++) {
            #pragma unroll
            for (int nt = 0; nt < 8; nt++) {
                int rr = rbase + mt * 16;
                int cc = cbase + nt * 8;
                size_t e0 = (size_t)rr * Cc + cc;
                size_t e1 = (size_t)(rr + 8) * Cc + cc;
                float2 m0 = *(const float2*)(v1 + e0);
                float2 m1 = *(const float2*)(v1 + e1);
                float a0 = (1.f - lam) * d[mt][nt][0] + lam * m0.x;
                float a1 = (1.f - lam) * d[mt][nt][1] + lam * m0.y;
                float a2 = (1.f - lam) * d[mt][nt][2] + lam * m1.x;
                float a3 = (1.f - lam) * d[mt][nt][3] + lam * m1.y;
                uint32_t hp, lp;
                split2pack(a0, a1, hp, lp);
                *(uint32_t*)(vhout + e0) = hp;
                *(uint32_t*)(vlout + e0) = lp;
                split2pack(a2, a3, hp, lp);
                *(uint32_t*)(vhout + e1) = hp;
                *(uint32_t*)(vlout + e1) = lp;
            }
        }
    }
}

// ---------------------------------------------------------------------------
// Proj GEMM (fp32 out, no mix) — same mainloop.
// ---------------------------------------------------------------------------
__global__ __launch_bounds__(256, 2) void gemm_bf(
    const uint16_t* __restrict__ Ah, const uint16_t* __restrict__ Al,
    const uint16_t* __restrict__ Wh, const uint16_t* __restrict__ Wl,
    float* __restrict__ Cout)
{
    extern __shared__ __align__(16) char dsm[];
    const uint32_t sbase = smem_u32(dsm);
    const int tid  = threadIdx.x;
    const int wid  = tid >> 5;
    const int lane = tid & 31;
    const int warp_r = wid & 3;
    const int warp_c = wid >> 2;
    const int row0 = blockIdx.x * 128;
    const int col0 = blockIdx.y * 128;

    float d[2][8][4];
    #pragma unroll
    for (int mt = 0; mt < 2; mt++)
        #pragma unroll
        for (int nt = 0; nt < 8; nt++)
            #pragma unroll
            for (int e = 0; e < 4; e++) d[mt][nt][e] = 0.f;

    GEMM_MAINLOOP(Ah, Al, Wh, Wl, row0, col0)

    const int rbase = row0 + warp_r * 32 + (lane >> 2);
    const int cbase = col0 + warp_c * 64 + (lane & 3) * 2;
    #pragma unroll
    for (int mt = 0; mt < 2; mt++) {
        #pragma unroll
        for (int nt = 0; nt < 8; nt++) {
            int rr = rbase + mt * 16;
            int cc = cbase + nt * 8;
            *(float2*)(Cout + (size_t)rr * Cc + cc) =
                make_float2(d[mt][nt][0], d[mt][nt][1]);
            *(float2*)(Cout + (size_t)(rr + 8) * Cc + cc) =
                make_float2(d[mt][nt][2], d[mt][nt][3]);
        }
    }
}

// ---------------------------------------------------------------------------
// RoPE tables (fp64 trig; immune to --use_fast_math substitution).
// ---------------------------------------------------------------------------
__global__ void rope_table_kernel(float* __restrict__ ctab,
                                  float* __restrict__ stab)
{
    int t    = blockIdx.x;
    int lane = threadIdx.x;
    float invf = (float)exp2(-(double)lane * (13.287712379549449 / 32.0));
    float fr   = __fmul_rn((float)t, invf);
    ctab[t * 32 + lane] = (float)cos((double)fr);
    stab[t * 32 + lane] = (float)sin((double)fr);
}

// ---------------------------------------------------------------------------
// RMSNorm + RoPE, fp32 in -> hi/lo bf16 out (q pre-scaled by 0.125).
// ---------------------------------------------------------------------------
__global__ __launch_bounds__(256) void rmsrope_split(
    const float* __restrict__ qsrc, const float* __restrict__ ksrc,
    uint16_t* __restrict__ qh, uint16_t* __restrict__ ql,
    uint16_t* __restrict__ kh, uint16_t* __restrict__ kl,
    const float* __restrict__ ctab, const float* __restrict__ stab)
{
    const int isk = blockIdx.y;
    const float* src = isk ? ksrc : qsrc;
    uint16_t* dh = isk ? kh : qh;
    uint16_t* dl = isk ? kl : ql;
    const float scale = isk ? 1.0f : 0.125f;

    const int warp = threadIdx.x >> 5;
    const int lane = threadIdx.x & 31;
    const int row  = blockIdx.x * 8 + warp;
    const int t    = (row / Hh) % Tt;

    const float* base = src + (size_t)row * 64;
    float x1 = base[lane];
    float x2 = base[lane + 32];

    float ss = x1 * x1 + x2 * x2;
    #pragma unroll
    for (int off = 16; off; off >>= 1)
        ss += __shfl_xor_sync(0xffffffffu, ss, off);

    float r = rsqrtf(ss * (1.0f / 64.0f) + 1.1920929e-7f);
    float c = __ldg(&ctab[t * 32 + lane]);
    float s = __ldg(&stab[t * 32 + lane]);

    float n1 = x1 * r, n2 = x2 * r;
    float y1 = (n1 * c + n2 * s) * scale;
    float y2 = (n2 * c - n1 * s) * scale;

    size_t o = (size_t)row * 64;
    __nv_bfloat16 h1 = __float2bfloat16(y1);
    __nv_bfloat16 h2 = __float2bfloat16(y2);
    __nv_bfloat16 l1 = __float2bfloat16(y1 - __bfloat162float(h1));
    __nv_bfloat16 l2 = __float2bfloat16(y2 - __bfloat162float(h2));
    dh[o + lane]      = *(unsigned short*)&h1;
    dh[o + lane + 32] = *(unsigned short*)&h2;
    dl[o + lane]      = *(unsigned short*)&l1;
    dl[o + lane + 32] = *(unsigned short*)&l2;
}

// ---------------------------------------------------------------------------
// Flash attention on mma.sync (bf16 hi/lo split), causal, online softmax.
// CTA: 512 threads, 256 queries x one (b,h); 16 warps x 16 q-rows.
// Key tiles of 64, cp.async double-buffered. 4 warps/SMSP.
// ---------------------------------------------------------------------------
#define FROWB 144              /* 72-element padded row, bytes */
#define F_QL 36864             /* Q lo array offset (Q hi at 0): 256 rows */
#define F_STG 73728            /* Q region total; KV stages follow */
#define F_STGB 36864           /* stage: Kh,Kl,Vh,Vl @ 9216 each */
#define FLASH_SMEM (F_STG + 2*F_STGB)   /* 147456 */

__global__ __launch_bounds__(512, 1) void flash_mma(
    const uint16_t* __restrict__ qh, const uint16_t* __restrict__ ql,
    const uint16_t* __restrict__ kh, const uint16_t* __restrict__ kl,
    const uint16_t* __restrict__ vh, const uint16_t* __restrict__ vl,
    uint16_t* __restrict__ oh, uint16_t* __restrict__ ol)
{
    extern __shared__ __align__(16) char fsm[];
    const uint32_t sb = smem_u32(fsm);
    const int tid = threadIdx.x;
    const int wid = tid >> 5;                        // 0..15
    const int lane = tid & 31;
    const int qblk = gridDim.x - 1 - blockIdx.x;     // heavy first
    const int bh = blockIdx.y;
    const int b = bh >> 4, h = bh & 15;
    const int q0 = qblk * 256;
    const int nkt = 4 * qblk + 4;
    const size_t rowbase = (size_t)b * Tt * Cc + (size_t)h * Dd;

    // stage loader: K/V hi+lo, 64 rows x 128B each (1 chunk/thread/array)
    #define F_ISSUE(st, kt)                                                     \
    do {                                                                        \
        uint32_t s_ = sb + F_STG + (uint32_t)(st) * F_STGB;                     \
        int k0_ = (kt) * 64;                                                    \
        int r_ = tid >> 3, cq_ = tid & 7;                                       \
        size_t g_ = rowbase + (size_t)(k0_ + r_) * Cc + cq_ * 8;                \
        uint32_t d_ = s_ + (uint32_t)(r_ * FROWB + cq_ * 16);                   \
        cp16(d_,         kh + g_);                                              \
        cp16(d_ +  9216, kl + g_);                                              \
        cp16(d_ + 18432, vh + g_);                                              \
        cp16(d_ + 27648, vl + g_);                                              \
    } while (0)

    // Prologue: Q (256 rows x 128B, hi+lo) + stage 0 in one group
    #pragma unroll
    for (int i = 0; i < 4; i++) {
        int c = tid + 512 * i;
        int r = c >> 3, cq = c & 7;
        size_t g = rowbase + (size_t)(q0 + r) * Cc + cq * 8;
        uint32_t d = sb + (uint32_t)(r * FROWB + cq * 16);
        cp16(d, qh + g);
        cp16(d + F_QL, ql + g);
    }
    F_ISSUE(0, 0);
    CP_COMMIT();

    const uint32_t a_off = (uint32_t)((16*wid + (lane & 15)) * FROWB + (lane >> 4) * 16);
    const uint32_t bk_off = (uint32_t)(((lane & 7) + ((lane >> 4) & 1) * 8) * FROWB
                                       + ((lane >> 3) & 1) * 16);
    const uint32_t bv_off = (uint32_t)(((lane & 7) + ((lane >> 3) & 1) * 8) * FROWB
                                       + ((lane >> 4) & 1) * 16);

    uint32_t qfh[4][4], qfl[4][4];
    float o[8][4];
    #pragma unroll
    for (int j = 0; j < 8; j++)
        #pragma unroll
        for (int e = 0; e < 4; e++) o[j][e] = 0.f;
    float mrow[2] = {-1e30f, -1e30f};
    float lrow[2] = {0.f, 0.f};

    for (int kt = 0; kt < nkt; kt++) {
        if (kt + 1 < nkt) {
            F_ISSUE((kt + 1) & 1, kt + 1);
            CP_COMMIT();
            CP_WAIT1();
        } else {
            CP_WAIT0();
        }
        __syncthreads();

        if (kt == 0) {
            #pragma unroll
            for (int ks = 0; ks < 4; ks++) {
                ldm4(qfh[ks], sb + a_off + ks * 32);
                ldm4(qfl[ks], sb + F_QL + a_off + ks * 32);
            }
        }

        const uint32_t stg = sb + F_STG + (uint32_t)(kt & 1) * F_STGB;

        // S = Qh*Kh + Qh*Kl + Ql*Kh
        float s[8][4];
        #pragma unroll
        for (int j = 0; j < 8; j++)
            #pragma unroll
            for (int e = 0; e < 4; e++) s[j][e] = 0.f;

        #pragma unroll
        for (int ks = 0; ks < 4; ks++) {
            #pragma unroll
            for (int g = 0; g < 4; g++) {
                uint32_t khf[4], klf[4];
                uint32_t off = bk_off + (uint32_t)g * 16 * FROWB + (uint32_t)ks * 32;
                ldm4(khf, stg + off);
                ldm4(klf, stg + 9216 + off);
                mma16816(s[2*g],   qfh[ks], khf[0], khf[1]);
                mma16816(s[2*g+1], qfh[ks], khf[2], khf[3]);
                mma16816(s[2*g],   qfh[ks], klf[0], klf[1]);
                mma16816(s[2*g+1], qfh[ks], klf[2], klf[3]);
                mma16816(s[2*g],   qfl[ks], khf[0], khf[1]);
                mma16816(s[2*g+1], qfl[ks], khf[2], khf[3]);
            }
        }

        // causal mask (only the last 4 key tiles can cross the diagonal)
        if (kt >= 4 * qblk) {
            int qg0 = q0 + 16 * wid + (lane >> 2);
            int kgb = kt * 64 + (lane & 3) * 2;
            #pragma unroll
            for (int j = 0; j < 8; j++) {
                int kg = kgb + j * 8;
                if (kg     > qg0)     s[j][0] = -1e30f;
                if (kg + 1 > qg0)     s[j][1] = -1e30f;
                if (kg     > qg0 + 8) s[j][2] = -1e30f;
                if (kg + 1 > qg0 + 8) s[j][3] = -1e30f;
            }
        }

        // online softmax (rows r = lane>>2 and r+8)
        float tm0 = -1e30f, tm1 = -1e30f;
        #pragma unroll
        for (int j = 0; j < 8; j++) {
            tm0 = fmaxf(tm0, fmaxf(s[j][0], s[j][1]));
            tm1 = fmaxf(tm1, fmaxf(s[j][2], s[j][3]));
        }
        tm0 = fmaxf(tm0, __shfl_xor_sync(0xffffffffu, tm0, 1));
        tm0 = fmaxf(tm0, __shfl_xor_sync(0xffffffffu, tm0, 2));
        tm1 = fmaxf(tm1, __shfl_xor_sync(0xffffffffu, tm1, 1));
        tm1 = fmaxf(tm1, __shfl_xor_sync(0xffffffffu, tm1, 2));
        float mn0 = fmaxf(mrow[0], tm0);
        float mn1 = fmaxf(mrow[1], tm1);
        float al0 = __expf(mrow[0] - mn0);
        float al1 = __expf(mrow[1] - mn1);
        float rs0 = 0.f, rs1 = 0.f;
        #pragma unroll
        for (int j = 0; j < 8; j++) {
            s[j][0] = __expf(s[j][0] - mn0);
            s[j][1] = __expf(s[j][1] - mn0);
            s[j][2] = __expf(s[j][2] - mn1);
            s[j][3] = __expf(s[j][3] - mn1);
            rs0 += s[j][0] + s[j][1];
            rs1 += s[j][2] + s[j][3];
        }
        rs0 += __shfl_xor_sync(0xffffffffu, rs0, 1);
        rs0 += __shfl_xor_sync(0xffffffffu, rs0, 2);
        rs1 += __shfl_xor_sync(0xffffffffu, rs1, 1);
        rs1 += __shfl_xor_sync(0xffffffffu, rs1, 2);
        lrow[0] = lrow[0] * al0 + rs0;
        lrow[1] = lrow[1] * al1 + rs1;
        mrow[0] = mn0;
        mrow[1] = mn1;
        #pragma unroll
        for (int j = 0; j < 8; j++) {
            o[j][0] *= al0; o[j][1] *= al0;
            o[j][2] *= al1; o[j][3] *= al1;
        }

        // P fragments (hi/lo), reusing the S accumulator layout as A layout
        uint32_t pfh[4][4], pfl[4][4];
        #pragma unroll
        for (int ks = 0; ks < 4; ks++) {
            split2pack(s[2*ks][0],   s[2*ks][1],   pfh[ks][0], pfl[ks][0]);
            split2pack(s[2*ks][2],   s[2*ks][3],   pfh[ks][1], pfl[ks][1]);
            split2pack(s[2*ks+1][0], s[2*ks+1][1], pfh[ks][2], pfl[ks][2]);
            split2pack(s[2*ks+1][2], s[2*ks+1][3], pfh[ks][3], pfl[ks][3]);
        }

        // O += Ph*Vh + Ph*Vl + Pl*Vh  (V via ldmatrix.trans from [key][dim])
        #pragma unroll
        for (int ks = 0; ks < 4; ks++) {
            #pragma unroll
            for (int g = 0; g < 4; g++) {
                uint32_t vhf[4], vlf[4];
                uint32_t off = bv_off + (uint32_t)ks * 16 * FROWB + (uint32_t)g * 32;
                ldm4t(vhf, stg + 18432 + off);
                ldm4t(vlf, stg + 27648 + off);
                mma16816(o[2*g],   pfh[ks], vhf[0], vhf[1]);
                mma16816(o[2*g+1], pfh[ks], vhf[2], vhf[3]);
                mma16816(o[2*g],   pfh[ks], vlf[0], vlf[1]);
                mma16816(o[2*g+1], pfh[ks], vlf[2], vlf[3]);
                mma16816(o[2*g],   pfl[ks], vhf[0], vhf[1]);
                mma16816(o[2*g+1], pfl[ks], vhf[2], vhf[3]);
            }
        }
        __syncthreads();
    }
    #undef F_ISSUE

    float inv0 = 1.0f / lrow[0];
    float inv1 = 1.0f / lrow[1];
    int t0 = q0 + 16 * wid + (lane >> 2);
    int t1 = t0 + 8;
    #pragma unroll
    for (int j = 0; j < 8; j++) {
        int cb = j * 8 + (lane & 3) * 2;
        size_t e0 = rowbase + (size_t)t0 * Cc + cb;
        size_t e1 = rowbase + (size_t)t1 * Cc + cb;
        uint32_t hp, lp;
        split2pack(o[j][0] * inv0, o[j][1] * inv0, hp, lp);
        *(uint32_t*)(oh + e0) = hp;
        *(uint32_t*)(ol + e0) = lp;
        split2pack(o[j][2] * inv1, o[j][3] * inv1, hp, lp);
        *(uint32_t*)(oh + e1) = hp;
        *(uint32_t*)(ol + e1) = lp;
    }
}

// ---------------------------------------------------------------------------
__global__ void copy_kernel(const float4* __restrict__ src,
                            float4* __restrict__ dst, int n4)
{
    for (int i = blockIdx.x * blockDim.x + threadIdx.x; i < n4;
         i += gridDim.x * blockDim.x)
        dst[i] = src[i];
}

// ---------------------------------------------------------------------------
extern "C" void kernel_launch(void* const* d_in, const int* in_sizes, int n_in,
                              void* d_out, int out_size)
{
    const float *x, *v1, *Wq, *Wk, *Wv, *Wp, *lamb;
    if (in_sizes[0] == Mm * Cc) {            // dict order
        x    = (const float*)d_in[0];
        v1   = (const float*)d_in[1];
        Wq   = (const float*)d_in[2];
        Wk   = (const float*)d_in[3];
        Wv   = (const float*)d_in[4];
        Wp   = (const float*)d_in[5];
        lamb = (const float*)d_in[6];
    } else {                                  // alphabetical order
        Wk   = (const float*)d_in[0];
        Wp   = (const float*)d_in[1];
        Wq   = (const float*)d_in[2];
        Wv   = (const float*)d_in[3];
        lamb = (const float*)d_in[4];
        v1   = (const float*)d_in[5];
        x    = (const float*)d_in[6];
    }
    float* out = (float*)d_out;

    float *q, *k, *ctab, *stab;
    uint16_t *xh, *xl, *wh, *wl, *qhp, *qlp, *khp, *klp, *vhp, *vlp;
    cudaGetSymbolAddress((void**)&q,    g_q);
    cudaGetSymbolAddress((void**)&k,    g_k);
    cudaGetSymbolAddress((void**)&ctab, g_cos);
    cudaGetSymbolAddress((void**)&stab, g_sin);
    cudaGetSymbolAddress((void**)&xh,   g_xh);
    cudaGetSymbolAddress((void**)&xl,   g_xl);
    cudaGetSymbolAddress((void**)&wh,   g_wh);
    cudaGetSymbolAddress((void**)&wl,   g_wl);
    cudaGetSymbolAddress((void**)&qhp,  g_qh);
    cudaGetSymbolAddress((void**)&qlp,  g_ql);
    cudaGetSymbolAddress((void**)&khp,  g_kh);
    cudaGetSymbolAddress((void**)&klp,  g_kl);
    cudaGetSymbolAddress((void**)&vhp,  g_vh);
    cudaGetSymbolAddress((void**)&vlp,  g_vl);

    rope_table_kernel<<<Tt, 32>>>(ctab, stab);

    const int nx4 = Mm * Cc / 4;
    const int nw4 = Cc * Cc / 4;
    split_kernel<<<(nx4 + 255) / 256, 256>>>((const float4*)x,
        (uint2*)xh, (uint2*)xl, nx4);
    split_w_kernel<<<(4 * nw4 + 255) / 256, 256>>>(
        (const float4*)Wq, (const float4*)Wk, (const float4*)Wv,
        (const float4*)Wp, (uint2*)wh, (uint2*)wl, nw4);

    cudaFuncSetAttribute(gemm_qkv,
                         cudaFuncAttributeMaxDynamicSharedMemorySize, GBF_SMEM);
    cudaFuncSetAttribute(gemm_bf,
                         cudaFuncAttributeMaxDynamicSharedMemorySize, GBF_SMEM);

    gemm_qkv<<<dim3(Mm / 128, Cc / 128, 3), 256, GBF_SMEM>>>(
        xh, xl, wh, wl, q, k, v1, lamb, vhp, vlp);

    rmsrope_split<<<dim3(Bb * Tt * Hh / 8, 2), 256>>>(q, k, qhp, qlp, khp, klp,
                                                      ctab, stab);

    cudaFuncSetAttribute(flash_mma,
                         cudaFuncAttributeMaxDynamicSharedMemorySize, FLASH_SMEM);
    flash_mma<<<dim3(Tt / 256, Bb * Hh), 512, FLASH_SMEM>>>(
        qhp, qlp, khp, klp, vhp, vlp, xh, xl);

    gemm_bf<<<dim3(Mm / 128, Cc / 128), 256, GBF_SMEM>>>(
        xh, xl, wh + 3ll*Cc*Cc, wl + 3ll*Cc*Cc, out);

    if (out_size >= 2 * Mm * Cc)
        copy_kernel<<<2048, 256>>>((const float4*)v1,
                                   (float4*)(out + (size_t)Mm * Cc),
                                   (Mm * Cc) / 4);
}

// round 17
// speedup vs baseline: 1.1666x; 1.1034x over previous
#include <cuda_runtime.h>
#include <cuda_bf16.h>
#include <cstdint>
#include <math.h>

#define Bb 4
#define Tt 2048
#define Cc 1024
#define Hh 16
#define Dd 64
#define Mm (Bb*Tt)   /* 8192 rows */

// Scratch (device globals: allocation-free rule)
__device__ float g_cos[Tt*32];
__device__ float g_sin[Tt*32];
// bf16 hi/lo split operands
__device__ uint16_t g_xh[Mm*Cc];   // x split; later reused for attention output
__device__ uint16_t g_xl[Mm*Cc];
__device__ uint16_t g_wh[4*Cc*Cc];
__device__ uint16_t g_wl[4*Cc*Cc];
__device__ uint16_t g_qh[Mm*Cc];
__device__ uint16_t g_ql[Mm*Cc];
__device__ uint16_t g_kh[Mm*Cc];
__device__ uint16_t g_kl[Mm*Cc];
__device__ uint16_t g_vh[Mm*Cc];
__device__ uint16_t g_vl[Mm*Cc];

// ========================== helpers ===========================
__device__ __forceinline__ uint32_t smem_u32(const void* p)
{
    uint32_t a;
    asm("{ .reg .u64 t; cvta.to.shared.u64 t, %1; cvt.u32.u64 %0, t; }"
        : "=r"(a) : "l"(p));
    return a;
}

__device__ __forceinline__ void ldm4(uint32_t* r, uint32_t addr)
{
    asm volatile("ldmatrix.sync.aligned.m8n8.x4.shared.b16 {%0,%1,%2,%3}, [%4];"
                 : "=r"(r[0]), "=r"(r[1]), "=r"(r[2]), "=r"(r[3])
                 : "r"(addr));
}

__device__ __forceinline__ void ldm4t(uint32_t* r, uint32_t addr)
{
    asm volatile("ldmatrix.sync.aligned.m8n8.x4.trans.shared.b16 {%0,%1,%2,%3}, [%4];"
                 : "=r"(r[0]), "=r"(r[1]), "=r"(r[2]), "=r"(r[3])
                 : "r"(addr));
}

__device__ __forceinline__ void mma16816(float* d, const uint32_t* a,
                                         uint32_t b0, uint32_t b1)
{
    asm volatile(
        "mma.sync.aligned.m16n8k16.row.col.f32.bf16.bf16.f32 "
        "{%0,%1,%2,%3}, {%4,%5,%6,%7}, {%8,%9}, {%0,%1,%2,%3};"
        : "+f"(d[0]), "+f"(d[1]), "+f"(d[2]), "+f"(d[3])
        : "r"(a[0]), "r"(a[1]), "r"(a[2]), "r"(a[3]), "r"(b0), "r"(b1));
}

__device__ __forceinline__ void cp16(uint32_t dst, const void* src)
{
    asm volatile("cp.async.cg.shared.global [%0], [%1], 16;"
                 :: "r"(dst), "l"(src));
}
#define CP_COMMIT() asm volatile("cp.async.commit_group;" ::: "memory")
#define CP_WAIT1()  asm volatile("cp.async.wait_group 1;"  ::: "memory")
#define CP_WAIT0()  asm volatile("cp.async.wait_group 0;"  ::: "memory")

__device__ __forceinline__ void split4(float4 a, uint2& hi4, uint2& lo4)
{
    __nv_bfloat16 h0 = __float2bfloat16(a.x), h1 = __float2bfloat16(a.y);
    __nv_bfloat16 h2 = __float2bfloat16(a.z), h3 = __float2bfloat16(a.w);
    __nv_bfloat16 l0 = __float2bfloat16(a.x - __bfloat162float(h0));
    __nv_bfloat16 l1 = __float2bfloat16(a.y - __bfloat162float(h1));
    __nv_bfloat16 l2 = __float2bfloat16(a.z - __bfloat162float(h2));
    __nv_bfloat16 l3 = __float2bfloat16(a.w - __bfloat162float(h3));
    unsigned short u0 = *(unsigned short*)&h0, u1 = *(unsigned short*)&h1;
    unsigned short u2 = *(unsigned short*)&h2, u3 = *(unsigned short*)&h3;
    unsigned short v0 = *(unsigned short*)&l0, v1 = *(unsigned short*)&l1;
    unsigned short v2 = *(unsigned short*)&l2, v3 = *(unsigned short*)&l3;
    hi4.x = (uint32_t)u0 | ((uint32_t)u1 << 16);
    hi4.y = (uint32_t)u2 | ((uint32_t)u3 << 16);
    lo4.x = (uint32_t)v0 | ((uint32_t)v1 << 16);
    lo4.y = (uint32_t)v2 | ((uint32_t)v3 << 16);
}

__device__ __forceinline__ void split2pack(float x, float y,
                                           uint32_t& hp, uint32_t& lp)
{
    __nv_bfloat16 hx = __float2bfloat16(x), hy = __float2bfloat16(y);
    __nv_bfloat16 lx = __float2bfloat16(x - __bfloat162float(hx));
    __nv_bfloat16 ly = __float2bfloat16(y - __bfloat162float(hy));
    unsigned short a = *(unsigned short*)&hx, b = *(unsigned short*)&hy;
    unsigned short c = *(unsigned short*)&lx, d = *(unsigned short*)&ly;
    hp = (uint32_t)a | ((uint32_t)b << 16);
    lp = (uint32_t)c | ((uint32_t)d << 16);
}

// ---------------------------------------------------------------------------
// fp32 -> (hi, lo) bf16 split, elementwise.
// ---------------------------------------------------------------------------
__global__ void split_kernel(const float4* __restrict__ src,
                             uint2* __restrict__ hi, uint2* __restrict__ lo,
                             int n4)
{
    int i = blockIdx.x * blockDim.x + threadIdx.x;
    if (i < n4) {
        uint2 h4, l4;
        split4(src[i], h4, l4);
        hi[i] = h4;
        lo[i] = l4;
    }
}

// All four weights in one launch.
__global__ void split_w_kernel(const float4* __restrict__ w0,
                               const float4* __restrict__ w1,
                               const float4* __restrict__ w2,
                               const float4* __restrict__ w3,
                               uint2* __restrict__ hi, uint2* __restrict__ lo,
                               int n4each)
{
    int i = blockIdx.x * blockDim.x + threadIdx.x;
    if (i < 4 * n4each) {
        int w = i / n4each;
        int j = i - w * n4each;
        const float4* src = (w == 0) ? w0 : (w == 1) ? w1 : (w == 2) ? w2 : w3;
        uint2 h4, l4;
        split4(src[j], h4, l4);
        hi[i] = h4;
        lo[i] = l4;
    }
}

// ---------------------------------------------------------------------------
// RoPE tables (fp64 trig; immune to --use_fast_math substitution).
// ---------------------------------------------------------------------------
__global__ void rope_table_kernel(float* __restrict__ ctab,
                                  float* __restrict__ stab)
{
    int t    = blockIdx.x;
    int lane = threadIdx.x;
    float invf = (float)exp2(-(double)lane * (13.287712379549449 / 32.0));
    float fr   = __fmul_rn((float)t, invf);
    ctab[t * 32 + lane] = (float)cos((double)fr);
    stab[t * 32 + lane] = (float)sin((double)fr);
}

// ---------------------------------------------------------------------------
// Shared GEMM mainloop, 2-stage ring, BK=32 (R14 proven config; 2 CTAs/SM).
// Accumulates d[2][8][4] for a 128x128 tile of sum_k A[m][k]*W[n][k].
// ---------------------------------------------------------------------------
#define SK 40
#define ARR_B (128*SK*2)
#define STG_B (4*ARR_B)
#define NSTG 2
#define GBF_SMEM (NSTG*STG_B)    /* 81920 B -> 2 CTAs/SM */

#define ISSUE_STAGE(st, kb)                                                       \
    do {                                                                          \
        uint32_t sb_ = sbase + (uint32_t)(st) * STG_B;                            \
        int koff_ = (kb) * 32;                                                    \
        { int r_ = cr0;                                                           \
          uint32_t doff_ = (uint32_t)(r_ * 80 + cc0 * 16);                        \
          size_t ga_ = (size_t)(row0 + r_) * Cc + koff_ + cc0 * 8;                \
          size_t gw_ = (size_t)(col0 + r_) * Cc + koff_ + cc0 * 8;                \
          cp16(sb_ + doff_,             Ah + ga_);                                \
          cp16(sb_ + ARR_B + doff_,     Al + ga_);                                \
          cp16(sb_ + 2*ARR_B + doff_,   Wh + gw_);                                \
          cp16(sb_ + 3*ARR_B + doff_,   Wl + gw_); }                              \
        { int r_ = cr0 + 64;                                                      \
          uint32_t doff_ = (uint32_t)(r_ * 80 + cc0 * 16);                        \
          size_t ga_ = (size_t)(row0 + r_) * Cc + koff_ + cc0 * 8;                \
          size_t gw_ = (size_t)(col0 + r_) * Cc + koff_ + cc0 * 8;                \
          cp16(sb_ + doff_,             Ah + ga_);                                \
          cp16(sb_ + ARR_B + doff_,     Al + ga_);                                \
          cp16(sb_ + 2*ARR_B + doff_,   Wh + gw_);                                \
          cp16(sb_ + 3*ARR_B + doff_,   Wl + gw_); }                              \
    } while (0)

#define GEMM_MAINLOOP(Ah, Al, Wh, Wl, row0, col0)                                 \
    const uint32_t a_elem = (uint32_t)((warp_r*32 + (lane & 15)) * SK + (lane >> 4) * 8); \
    const uint32_t b_elem = (uint32_t)((warp_c*64 + (lane & 7) + ((lane >> 4) & 1) * 8) * SK \
                                       + ((lane >> 3) & 1) * 8);                  \
    const int cr0 = tid >> 2;                                                     \
    const int cc0 = tid & 3;                                                      \
    ISSUE_STAGE(0, 0); CP_COMMIT();                                               \
    ISSUE_STAGE(1, 1); CP_COMMIT();                                               \
    for (int kb = 0; kb < 32; kb++) {                                             \
        CP_WAIT1();                                                               \
        __syncthreads();                                                          \
        const uint32_t sb = sbase + (uint32_t)(kb & 1) * STG_B;                   \
        const uint32_t ah_b = sb;                                                 \
        const uint32_t al_b = sb + ARR_B;                                         \
        const uint32_t wh_b = sb + 2*ARR_B;                                       \
        const uint32_t wl_b = sb + 3*ARR_B;                                       \
        _Pragma("unroll")                                                         \
        for (int ks = 0; ks < 2; ks++) {                                          \
            uint32_t ahf[2][4], alf[2][4];                                        \
            _Pragma("unroll")                                                     \
            for (int mt = 0; mt < 2; mt++) {                                      \
                uint32_t off = 2u * (a_elem + (uint32_t)mt * 16 * SK + (uint32_t)ks * 16); \
                ldm4(ahf[mt], ah_b + off);                                        \
                ldm4(alf[mt], al_b + off);                                        \
            }                                                                     \
            uint32_t bh[4][4], bl[4][4];                                          \
            _Pragma("unroll")                                                     \
            for (int g = 0; g < 4; g++) {                                         \
                uint32_t off = 2u * (b_elem + (uint32_t)g * 16 * SK + (uint32_t)ks * 16); \
                ldm4(bh[g], wh_b + off);                                          \
                ldm4(bl[g], wl_b + off);                                          \
            }                                                                     \
            _Pragma("unroll")                                                     \
            for (int mt = 0; mt < 2; mt++) {                                      \
                _Pragma("unroll")                                                 \
                for (int g = 0; g < 4; g++) {                                     \
                    mma16816(d[mt][2*g],   ahf[mt], bh[g][0], bh[g][1]);          \
                    mma16816(d[mt][2*g+1], ahf[mt], bh[g][2], bh[g][3]);          \
                    mma16816(d[mt][2*g],   ahf[mt], bl[g][0], bl[g][1]);          \
                    mma16816(d[mt][2*g+1], ahf[mt], bl[g][2], bl[g][3]);          \
                    mma16816(d[mt][2*g],   alf[mt], bh[g][0], bh[g][1]);          \
                    mma16816(d[mt][2*g+1], alf[mt], bh[g][2], bh[g][3]);          \
                }                                                                 \
            }                                                                     \
        }                                                                         \
        __syncthreads();                                                          \
        if (kb + 2 < 32) {                                                        \
            ISSUE_STAGE(kb & 1, kb + 2);                                          \
            CP_COMMIT();                                                          \
        }                                                                         \
    }

// ---------------------------------------------------------------------------
// Fused QKV GEMM with epilogues:
//   z<2 : RMSNorm + RoPE + bf16 hi/lo split -> qh/ql (z=0, x0.125) or kh/kl.
//         Warp's 64-col block == one head; row lives in one quad; RoPE pair
//         (j, j+32) == accumulators nt and nt+4 in the SAME thread.
//   z==2: lambda-mix with v1 -> vh/vl.
// ---------------------------------------------------------------------------
__global__ __launch_bounds__(256, 2) void gemm_qkv(
    const uint16_t* __restrict__ Ah, const uint16_t* __restrict__ Al,
    const uint16_t* __restrict__ WhB, const uint16_t* __restrict__ WlB,
    uint16_t* __restrict__ qhout, uint16_t* __restrict__ qlout,
    uint16_t* __restrict__ khout, uint16_t* __restrict__ klout,
    const float* __restrict__ v1, const float* __restrict__ lambp,
    uint16_t* __restrict__ vhout, uint16_t* __restrict__ vlout,
    const float* __restrict__ ctab, const float* __restrict__ stab)
{
    extern __shared__ __align__(16) char dsm[];
    const uint32_t sbase = smem_u32(dsm);
    const int tid  = threadIdx.x;
    const int wid  = tid >> 5;
    const int lane = tid & 31;
    const int warp_r = wid & 3;
    const int warp_c = wid >> 2;
    const int row0 = blockIdx.x * 128;
    const int col0 = blockIdx.y * 128;
    const int z = blockIdx.z;
    const uint16_t* Wh = WhB + (size_t)z * Cc * Cc;
    const uint16_t* Wl = WlB + (size_t)z * Cc * Cc;

    float d[2][8][4];
    #pragma unroll
    for (int mt = 0; mt < 2; mt++)
        #pragma unroll
        for (int nt = 0; nt < 8; nt++)
            #pragma unroll
            for (int e = 0; e < 4; e++) d[mt][nt][e] = 0.f;

    GEMM_MAINLOOP(Ah, Al, Wh, Wl, row0, col0)

    const int rbase = row0 + warp_r * 32 + (lane >> 2);
    const int cbase = col0 + warp_c * 64 + (lane & 3) * 2;
    if (z < 2) {
        const float scale = z ? 1.0f : 0.125f;
        uint16_t* dh = z ? khout : qhout;
        uint16_t* dl = z ? klout : qlout;
        const int hcol = col0 + warp_c * 64;      // head-aligned column base
        #pragma unroll
        for (int mt = 0; mt < 2; mt++) {
            #pragma unroll
            for (int half = 0; half < 2; half++) {
                int rr = rbase + mt * 16 + half * 8;
                int t  = rr & (Tt - 1);
                float ss = 0.f;
                #pragma unroll
                for (int nt = 0; nt < 8; nt++) {
                    float a  = d[mt][nt][half * 2];
                    float b2 = d[mt][nt][half * 2 + 1];
                    ss += a * a + b2 * b2;
                }
                ss += __shfl_xor_sync(0xffffffffu, ss, 1);
                ss += __shfl_xor_sync(0xffffffffu, ss, 2);
                float r = rsqrtf(ss * (1.0f / 64.0f) + 1.1920929e-7f);
                #pragma unroll
                for (int nt = 0; nt < 4; nt++) {
                    int jb = (lane & 3) * 2 + nt * 8;      // 0..30, even
                    float n1a = d[mt][nt][half * 2]     * r;
                    float n1b = d[mt][nt][half * 2 + 1] * r;
                    float n2a = d[mt][nt + 4][half * 2]     * r;
                    float n2b = d[mt][nt + 4][half * 2 + 1] * r;
                    float c0 = __ldg(&ctab[t * 32 + jb]);
                    float s0 = __ldg(&stab[t * 32 + jb]);
                    float c1 = __ldg(&ctab[t * 32 + jb + 1]);
                    float s1 = __ldg(&stab[t * 32 + jb + 1]);
                    float y1a = (n1a * c0 + n2a * s0) * scale;
                    float y1b = (n1b * c1 + n2b * s1) * scale;
                    float y2a = (n2a * c0 - n1a * s0) * scale;
                    float y2b = (n2b * c1 - n1b * s1) * scale;
                    size_t e0 = (size_t)rr * Cc + hcol + jb;
                    size_t e1 = e0 + 32;
                    uint32_t hp, lp;
                    split2pack(y1a, y1b, hp, lp);
                    *(uint32_t*)(dh + e0) = hp;
                    *(uint32_t*)(dl + e0) = lp;
                    split2pack(y2a, y2b, hp, lp);
                    *(uint32_t*)(dh + e1) = hp;
                    *(uint32_t*)(dl + e1) = lp;
                }
            }
        }
    } else {
        const float lam = *lambp;
        #pragma unroll
        for (int mt = 0; mt < 2; mt++) {
            #pragma unroll
            for (int nt = 0; nt < 8; nt++) {
                int rr = rbase + mt * 16;
                int cc = cbase + nt * 8;
                size_t e0 = (size_t)rr * Cc + cc;
                size_t e1 = (size_t)(rr + 8) * Cc + cc;
                float2 m0 = *(const float2*)(v1 + e0);
                float2 m1 = *(const float2*)(v1 + e1);
                float a0 = (1.f - lam) * d[mt][nt][0] + lam * m0.x;
                float a1 = (1.f - lam) * d[mt][nt][1] + lam * m0.y;
                float a2 = (1.f - lam) * d[mt][nt][2] + lam * m1.x;
                float a3 = (1.f - lam) * d[mt][nt][3] + lam * m1.y;
                uint32_t hp, lp;
                split2pack(a0, a1, hp, lp);
                *(uint32_t*)(vhout + e0) = hp;
                *(uint32_t*)(vlout + e0) = lp;
                split2pack(a2, a3, hp, lp);
                *(uint32_t*)(vhout + e1) = hp;
                *(uint32_t*)(vlout + e1) = lp;
            }
        }
    }
}

// ---------------------------------------------------------------------------
// Proj GEMM (fp32 out, no mix) — same mainloop.
// ---------------------------------------------------------------------------
__global__ __launch_bounds__(256, 2) void gemm_bf(
    const uint16_t* __restrict__ Ah, const uint16_t* __restrict__ Al,
    const uint16_t* __restrict__ Wh, const uint16_t* __restrict__ Wl,
    float* __restrict__ Cout)
{
    extern __shared__ __align__(16) char dsm[];
    const uint32_t sbase = smem_u32(dsm);
    const int tid  = threadIdx.x;
    const int wid  = tid >> 5;
    const int lane = tid & 31;
    const int warp_r = wid & 3;
    const int warp_c = wid >> 2;
    const int row0 = blockIdx.x * 128;
    const int col0 = blockIdx.y * 128;

    float d[2][8][4];
    #pragma unroll
    for (int mt = 0; mt < 2; mt++)
        #pragma unroll
        for (int nt = 0; nt < 8; nt++)
            #pragma unroll
            for (int e = 0; e < 4; e++) d[mt][nt][e] = 0.f;

    GEMM_MAINLOOP(Ah, Al, Wh, Wl, row0, col0)

    const int rbase = row0 + warp_r * 32 + (lane >> 2);
    const int cbase = col0 + warp_c * 64 + (lane & 3) * 2;
    #pragma unroll
    for (int mt = 0; mt < 2; mt++) {
        #pragma unroll
        for (int nt = 0; nt < 8; nt++) {
            int rr = rbase + mt * 16;
            int cc = cbase + nt * 8;
            *(float2*)(Cout + (size_t)rr * Cc + cc) =
                make_float2(d[mt][nt][0], d[mt][nt][1]);
            *(float2*)(Cout + (size_t)(rr + 8) * Cc + cc) =
                make_float2(d[mt][nt][2], d[mt][nt][3]);
        }
    }
}

// ---------------------------------------------------------------------------
// Flash attention on mma.sync (bf16 hi/lo split), causal (R14-exact).
// CTA: 256 threads, 128 queries x one (b,h); 64-key tiles, double-buffered.
// ---------------------------------------------------------------------------
#define FROWB 144
#define F_QL 18432
#define F_STG 36864
#define F_STGB 36864
#define FLASH_SMEM (F_STG + 2*F_STGB)   /* 110592 */

__global__ __launch_bounds__(256, 1) void flash_mma(
    const uint16_t* __restrict__ qh, const uint16_t* __restrict__ ql,
    const uint16_t* __restrict__ kh, const uint16_t* __restrict__ kl,
    const uint16_t* __restrict__ vh, const uint16_t* __restrict__ vl,
    uint16_t* __restrict__ oh, uint16_t* __restrict__ ol)
{
    extern __shared__ __align__(16) char fsm[];
    const uint32_t sb = smem_u32(fsm);
    const int tid = threadIdx.x;
    const int wid = tid >> 5;
    const int lane = tid & 31;
    const int qblk = gridDim.x - 1 - blockIdx.x;
    const int bh = blockIdx.y;
    const int b = bh >> 4, h = bh & 15;
    const int q0 = qblk * 128;
    const int nkt = 2 * qblk + 2;
    const size_t rowbase = (size_t)b * Tt * Cc + (size_t)h * Dd;

    #define F_ISSUE(st, kt)                                                     \
    do {                                                                        \
        uint32_t s_ = sb + F_STG + (uint32_t)(st) * F_STGB;                     \
        int k0_ = (kt) * 64;                                                    \
        _Pragma("unroll")                                                       \
        for (int i_ = 0; i_ < 2; i_++) {                                        \
            int c_ = tid + 256 * i_;                                            \
            int r_ = c_ >> 3, cq_ = c_ & 7;                                     \
            size_t g_ = rowbase + (size_t)(k0_ + r_) * Cc + cq_ * 8;            \
            uint32_t d_ = s_ + (uint32_t)(r_ * FROWB + cq_ * 16);               \
            cp16(d_,         kh + g_);                                          \
            cp16(d_ +  9216, kl + g_);                                          \
            cp16(d_ + 18432, vh + g_);                                          \
            cp16(d_ + 27648, vl + g_);                                          \
        }                                                                       \
    } while (0)

    #pragma unroll
    for (int i = 0; i < 4; i++) {
        int c = tid + 256 * i;
        int r = c >> 3, cq = c & 7;
        size_t g = rowbase + (size_t)(q0 + r) * Cc + cq * 8;
        uint32_t d = sb + (uint32_t)(r * FROWB + cq * 16);
        cp16(d, qh + g);
        cp16(d + F_QL, ql + g);
    }
    F_ISSUE(0, 0);
    CP_COMMIT();

    const uint32_t a_off = (uint32_t)((16*wid + (lane & 15)) * FROWB + (lane >> 4) * 16);
    const uint32_t bk_off = (uint32_t)(((lane & 7) + ((lane >> 4) & 1) * 8) * FROWB
                                       + ((lane >> 3) & 1) * 16);
    const uint32_t bv_off = (uint32_t)(((lane & 7) + ((lane >> 3) & 1) * 8) * FROWB
                                       + ((lane >> 4) & 1) * 16);

    uint32_t qfh[4][4], qfl[4][4];
    float o[8][4];
    #pragma unroll
    for (int j = 0; j < 8; j++)
        #pragma unroll
        for (int e = 0; e < 4; e++) o[j][e] = 0.f;
    float mrow[2] = {-1e30f, -1e30f};
    float lrow[2] = {0.f, 0.f};

    for (int kt = 0; kt < nkt; kt++) {
        if (kt + 1 < nkt) {
            F_ISSUE((kt + 1) & 1, kt + 1);
            CP_COMMIT();
            CP_WAIT1();
        } else {
            CP_WAIT0();
        }
        __syncthreads();

        if (kt == 0) {
            #pragma unroll
            for (int ks = 0; ks < 4; ks++) {
                ldm4(qfh[ks], sb + a_off + ks * 32);
                ldm4(qfl[ks], sb + F_QL + a_off + ks * 32);
            }
        }

        const uint32_t stg = sb + F_STG + (uint32_t)(kt & 1) * F_STGB;

        float s[8][4];
        #pragma unroll
        for (int j = 0; j < 8; j++)
            #pragma unroll
            for (int e = 0; e < 4; e++) s[j][e] = 0.f;

        #pragma unroll
        for (int ks = 0; ks < 4; ks++) {
            #pragma unroll
            for (int g = 0; g < 4; g++) {
                uint32_t khf[4], klf[4];
                uint32_t off = bk_off + (uint32_t)g * 16 * FROWB + (uint32_t)ks * 32;
                ldm4(khf, stg + off);
                ldm4(klf, stg + 9216 + off);
                mma16816(s[2*g],   qfh[ks], khf[0], khf[1]);
                mma16816(s[2*g+1], qfh[ks], khf[2], khf[3]);
                mma16816(s[2*g],   qfh[ks], klf[0], klf[1]);
                mma16816(s[2*g+1], qfh[ks], klf[2], klf[3]);
                mma16816(s[2*g],   qfl[ks], khf[0], khf[1]);
                mma16816(s[2*g+1], qfl[ks], khf[2], khf[3]);
            }
        }

        if (kt >= 2 * qblk) {
            int qg0 = q0 + 16 * wid + (lane >> 2);
            int kgb = kt * 64 + (lane & 3) * 2;
            #pragma unroll
            for (int j = 0; j < 8; j++) {
                int kg = kgb + j * 8;
                if (kg     > qg0)     s[j][0] = -1e30f;
                if (kg + 1 > qg0)     s[j][1] = -1e30f;
                if (kg     > qg0 + 8) s[j][2] = -1e30f;
                if (kg + 1 > qg0 + 8) s[j][3] = -1e30f;
            }
        }

        float tm0 = -1e30f, tm1 = -1e30f;
        #pragma unroll
        for (int j = 0; j < 8; j++) {
            tm0 = fmaxf(tm0, fmaxf(s[j][0], s[j][1]));
            tm1 = fmaxf(tm1, fmaxf(s[j][2], s[j][3]));
        }
        tm0 = fmaxf(tm0, __shfl_xor_sync(0xffffffffu, tm0, 1));
        tm0 = fmaxf(tm0, __shfl_xor_sync(0xffffffffu, tm0, 2));
        tm1 = fmaxf(tm1, __shfl_xor_sync(0xffffffffu, tm1, 1));
        tm1 = fmaxf(tm1, __shfl_xor_sync(0xffffffffu, tm1, 2));
        float mn0 = fmaxf(mrow[0], tm0);
        float mn1 = fmaxf(mrow[1], tm1);
        float al0 = __expf(mrow[0] - mn0);
        float al1 = __expf(mrow[1] - mn1);
        float rs0 = 0.f, rs1 = 0.f;
        #pragma unroll
        for (int j = 0; j < 8; j++) {
            s[j][0] = __expf(s[j][0] - mn0);
            s[j][1] = __expf(s[j][1] - mn0);
            s[j][2] = __expf(s[j][2] - mn1);
            s[j][3] = __expf(s[j][3] - mn1);
            rs0 += s[j][0] + s[j][1];
            rs1 += s[j][2] + s[j][3];
        }
        rs0 += __shfl_xor_sync(0xffffffffu, rs0, 1);
        rs0 += __shfl_xor_sync(0xffffffffu, rs0, 2);
        rs1 += __shfl_xor_sync(0xffffffffu, rs1, 1);
        rs1 += __shfl_xor_sync(0xffffffffu, rs1, 2);
        lrow[0] = lrow[0] * al0 + rs0;
        lrow[1] = lrow[1] * al1 + rs1;
        mrow[0] = mn0;
        mrow[1] = mn1;
        #pragma unroll
        for (int j = 0; j < 8; j++) {
            o[j][0] *= al0; o[j][1] *= al0;
            o[j][2] *= al1; o[j][3] *= al1;
        }

        uint32_t pfh[4][4], pfl[4][4];
        #pragma unroll
        for (int ks = 0; ks < 4; ks++) {
            split2pack(s[2*ks][0],   s[2*ks][1],   pfh[ks][0], pfl[ks][0]);
            split2pack(s[2*ks][2],   s[2*ks][3],   pfh[ks][1], pfl[ks][1]);
            split2pack(s[2*ks+1][0], s[2*ks+1][1], pfh[ks][2], pfl[ks][2]);
            split2pack(s[2*ks+1][2], s[2*ks+1][3], pfh[ks][3], pfl[ks][3]);
        }

        #pragma unroll
        for (int ks = 0; ks < 4; ks++) {
            #pragma unroll
            for (int g = 0; g < 4; g++) {
                uint32_t vhf[4], vlf[4];
                uint32_t off = bv_off + (uint32_t)ks * 16 * FROWB + (uint32_t)g * 32;
                ldm4t(vhf, stg + 18432 + off);
                ldm4t(vlf, stg + 27648 + off);
                mma16816(o[2*g],   pfh[ks], vhf[0], vhf[1]);
                mma16816(o[2*g+1], pfh[ks], vhf[2], vhf[3]);
                mma16816(o[2*g],   pfh[ks], vlf[0], vlf[1]);
                mma16816(o[2*g+1], pfh[ks], vlf[2], vlf[3]);
                mma16816(o[2*g],   pfl[ks], vhf[0], vhf[1]);
                mma16816(o[2*g+1], pfl[ks], vhf[2], vhf[3]);
            }
        }
        __syncthreads();
    }
    #undef F_ISSUE

    float inv0 = 1.0f / lrow[0];
    float inv1 = 1.0f / lrow[1];
    int t0 = q0 + 16 * wid + (lane >> 2);
    int t1 = t0 + 8;
    #pragma unroll
    for (int j = 0; j < 8; j++) {
        int cb = j * 8 + (lane & 3) * 2;
        size_t e0 = rowbase + (size_t)t0 * Cc + cb;
        size_t e1 = rowbase + (size_t)t1 * Cc + cb;
        uint32_t hp, lp;
        split2pack(o[j][0] * inv0, o[j][1] * inv0, hp, lp);
        *(uint32_t*)(oh + e0) = hp;
        *(uint32_t*)(ol + e0) = lp;
        split2pack(o[j][2] * inv1, o[j][3] * inv1, hp, lp);
        *(uint32_t*)(oh + e1) = hp;
        *(uint32_t*)(ol + e1) = lp;
    }
}

// ---------------------------------------------------------------------------
__global__ void copy_kernel(const float4* __restrict__ src,
                            float4* __restrict__ dst, int n4)
{
    for (int i = blockIdx.x * blockDim.x + threadIdx.x; i < n4;
         i += gridDim.x * blockDim.x)
        dst[i] = src[i];
}

// ---------------------------------------------------------------------------
extern "C" void kernel_launch(void* const* d_in, const int* in_sizes, int n_in,
                              void* d_out, int out_size)
{
    const float *x, *v1, *Wq, *Wk, *Wv, *Wp, *lamb;
    if (in_sizes[0] == Mm * Cc) {            // dict order
        x    = (const float*)d_in[0];
        v1   = (const float*)d_in[1];
        Wq   = (const float*)d_in[2];
        Wk   = (const float*)d_in[3];
        Wv   = (const float*)d_in[4];
        Wp   = (const float*)d_in[5];
        lamb = (const float*)d_in[6];
    } else {                                  // alphabetical order
        Wk   = (const float*)d_in[0];
        Wp   = (const float*)d_in[1];
        Wq   = (const float*)d_in[2];
        Wv   = (const float*)d_in[3];
        lamb = (const float*)d_in[4];
        v1   = (const float*)d_in[5];
        x    = (const float*)d_in[6];
    }
    float* out = (float*)d_out;

    float *ctab, *stab;
    uint16_t *xh, *xl, *wh, *wl, *qhp, *qlp, *khp, *klp, *vhp, *vlp;
    cudaGetSymbolAddress((void**)&ctab, g_cos);
    cudaGetSymbolAddress((void**)&stab, g_sin);
    cudaGetSymbolAddress((void**)&xh,   g_xh);
    cudaGetSymbolAddress((void**)&xl,   g_xl);
    cudaGetSymbolAddress((void**)&wh,   g_wh);
    cudaGetSymbolAddress((void**)&wl,   g_wl);
    cudaGetSymbolAddress((void**)&qhp,  g_qh);
    cudaGetSymbolAddress((void**)&qlp,  g_ql);
    cudaGetSymbolAddress((void**)&khp,  g_kh);
    cudaGetSymbolAddress((void**)&klp,  g_kl);
    cudaGetSymbolAddress((void**)&vhp,  g_vh);
    cudaGetSymbolAddress((void**)&vlp,  g_vl);

    rope_table_kernel<<<Tt, 32>>>(ctab, stab);

    const int nx4 = Mm * Cc / 4;
    const int nw4 = Cc * Cc / 4;
    split_kernel<<<(nx4 + 255) / 256, 256>>>((const float4*)x,
        (uint2*)xh, (uint2*)xl, nx4);
    split_w_kernel<<<(4 * nw4 + 255) / 256, 256>>>(
        (const float4*)Wq, (const float4*)Wk, (const float4*)Wv,
        (const float4*)Wp, (uint2*)wh, (uint2*)wl, nw4);

    cudaFuncSetAttribute(gemm_qkv,
                         cudaFuncAttributeMaxDynamicSharedMemorySize, GBF_SMEM);
    cudaFuncSetAttribute(gemm_bf,
                         cudaFuncAttributeMaxDynamicSharedMemorySize, GBF_SMEM);

    gemm_qkv<<<dim3(Mm / 128, Cc / 128, 3), 256, GBF_SMEM>>>(
        xh, xl, wh, wl, qhp, qlp, khp, klp, v1, lamb, vhp, vlp, ctab, stab);

    cudaFuncSetAttribute(flash_mma,
                         cudaFuncAttributeMaxDynamicSharedMemorySize, FLASH_SMEM);
    flash_mma<<<dim3(Tt / 128, Bb * Hh), 256, FLASH_SMEM>>>(
        qhp, qlp, khp, klp, vhp, vlp, xh, xl);

    gemm_bf<<<dim3(Mm / 128, Cc / 128), 256, GBF_SMEM>>>(
        xh, xl, wh + 3ll*Cc*Cc, wl + 3ll*Cc*Cc, out);

    if (out_size >= 2 * Mm * Cc)
        copy_kernel<<<2048, 256>>>((const float4*)v1,
                                   (float4*)(out + (size_t)Mm * Cc),
                                   (Mm * Cc) / 4);
}